// round 11
// baseline (speedup 1.0000x reference)
#include <cuda_runtime.h>
#include <cuda_bf16.h>
#include <math.h>
#include <cstdint>

// Problem constants
#define B_    8
#define CIN   128
#define H_    64
#define W_    64
#define HW    (H_ * W_)        // 4096
#define COUT  256
#define KK9   9
#define OC18  18
#define KD    (CIN * KK9)      // 1152
#define NCHK  4                // offset-conv channel chunks
#define CCH   (CIN / NCHK)     // 32

// ---------------- scratch (device globals; no allocation allowed) -----------
__device__ float g_offp[NCHK * B_ * OC18 * HW];               // offset partials
__device__ __nv_bfloat16 g_Phi[(size_t)B_ * KD * HW];         // P hi [b][k][n]
__device__ __nv_bfloat16 g_Plo[(size_t)B_ * KD * HW];         // P lo
__device__ __nv_bfloat16 g_Whi[COUT * KD];                    // W hi [m][k]
__device__ __nv_bfloat16 g_Wlo[COUT * KD];
__device__ float g_sum[COUT];
__device__ float g_sqs[COUT];
__device__ float g_mean[COUT];
__device__ float g_rstd[COUT];

// ============================================================================
// PTX helpers (plain sm_80+ instructions — compile for compute_103)
// ============================================================================
__device__ __forceinline__ uint32_t smem_u32(const void* p) {
    uint32_t a;
    asm("{ .reg .u64 t; cvta.to.shared.u64 t, %1; cvt.u32.u64 %0, t; }"
        : "=r"(a) : "l"(p));
    return a;
}
__device__ __forceinline__ void cpa16(uint32_t s, const void* g) {
    asm volatile("cp.async.cg.shared.global [%0], [%1], 16;" :: "r"(s), "l"(g));
}
#define CPA_COMMIT() asm volatile("cp.async.commit_group;" ::: "memory")
#define CPA_WAIT(N)  asm volatile("cp.async.wait_group %0;" :: "n"(N) : "memory")

__device__ __forceinline__ void ldsm4(uint32_t* r, uint32_t a) {
    asm volatile("ldmatrix.sync.aligned.m8n8.x4.shared.b16 {%0,%1,%2,%3}, [%4];"
                 : "=r"(r[0]), "=r"(r[1]), "=r"(r[2]), "=r"(r[3]) : "r"(a));
}
__device__ __forceinline__ void ldsm4t(uint32_t& r0, uint32_t& r1,
                                       uint32_t& r2, uint32_t& r3, uint32_t a) {
    asm volatile("ldmatrix.sync.aligned.m8n8.x4.trans.shared.b16 {%0,%1,%2,%3}, [%4];"
                 : "=r"(r0), "=r"(r1), "=r"(r2), "=r"(r3) : "r"(a));
}
__device__ __forceinline__ void mma16816(float* d, const uint32_t* a,
                                         const uint32_t* b) {
    asm volatile(
        "mma.sync.aligned.m16n8k16.row.col.f32.bf16.bf16.f32 "
        "{%0,%1,%2,%3}, {%4,%5,%6,%7}, {%8,%9}, {%0,%1,%2,%3};"
        : "+f"(d[0]), "+f"(d[1]), "+f"(d[2]), "+f"(d[3])
        : "r"(a[0]), "r"(a[1]), "r"(a[2]), "r"(a[3]), "r"(b[0]), "r"(b[1]));
}

// ============================================================================
// Kernel A: offset conv partials, smem-tiled x (each x element read once).
// Block = 2 rows x 64 cols of one batch, one 32-channel chunk.
// Grid: (256 = 8 batches * 32 row-blocks, NCHK).
// ============================================================================
__global__ void offset_conv_part_kernel(const float* __restrict__ x,
                                        const float* __restrict__ w) {
    __shared__ float ws[OC18 * CCH * 9];       // 20736 B
    __shared__ float xs[CCH][4][W_];           // 32768 B (4 rows incl. halo)
    int cc  = blockIdx.y;
    int tid = threadIdx.x;                     // 128

    for (int i = tid; i < OC18 * CCH * 9; i += 128) {
        int oc = i / (CCH * 9);
        int r  = i - oc * (CCH * 9);
        ws[i] = w[oc * KD + cc * (CCH * 9) + r];
    }

    int blk    = blockIdx.x;       // 0..255
    int b      = blk >> 5;         // batch
    int rowblk = blk & 31;         // 0..31
    int y0     = rowblk * 2;

    // stage x rows y0-1 .. y0+2 for 32 channels (zero-fill out-of-range rows)
    const float* xbase = x + ((size_t)b * CIN + cc * CCH) * HW;
    for (int i = tid; i < CCH * 4 * W_; i += 128) {
        int c   = i >> 8;            // /256
        int rem = i & 255;
        int r   = rem >> 6;          // 0..3
        int col = rem & 63;
        int gy  = y0 - 1 + r;
        float v = 0.f;
        if ((unsigned)gy < (unsigned)H_)
            v = xbase[(size_t)c * HW + gy * W_ + col];
        xs[c][r][col] = v;
    }
    __syncthreads();

    int ly = tid >> 6;             // 0/1
    int xx = tid & 63;
    int y  = y0 + ly;

    float acc[OC18];
#pragma unroll
    for (int oc = 0; oc < OC18; oc++) acc[oc] = 0.f;

    for (int c = 0; c < CCH; c++) {
        float v[9];
#pragma unroll
        for (int ky = 0; ky < 3; ky++) {
#pragma unroll
            for (int kx = 0; kx < 3; kx++) {
                int x2 = xx - 1 + kx;
                bool xv = (unsigned)x2 < (unsigned)W_;
                v[ky * 3 + kx] = xv ? xs[c][ly + ky][x2] : 0.f;
            }
        }
#pragma unroll
        for (int kk = 0; kk < 9; kk++) {
            float xvv = v[kk];
#pragma unroll
            for (int oc = 0; oc < OC18; oc++)
                acc[oc] = fmaf(xvv, ws[oc * (CCH * 9) + c * 9 + kk], acc[oc]);
        }
    }

    int pix = y * W_ + xx;
    float* ob = g_offp + (((size_t)cc * B_ + b) * OC18) * HW + pix;
#pragma unroll
    for (int oc = 0; oc < OC18; oc++) ob[(size_t)oc * HW] = acc[oc];
}

// ============================================================================
// Kernel B: deformable bilinear gather, 4 pixels/thread -> 8B packed stores
// ============================================================================
__global__ void gather_kernel(const float* __restrict__ x,
                              const float* __restrict__ offset_b,
                              __nv_bfloat16* __restrict__ Phi,
                              __nv_bfloat16* __restrict__ Plo) {
    int gid = blockIdx.x * blockDim.x + threadIdx.x;    // < 73728
    int p4  = gid & 1023;           // pixel quad
    int t   = gid >> 10;            // b*9 + kk
    int kk  = t % 9;
    int b   = t / 9;
    int n0  = p4 * 4;

    float bdy = offset_b[2 * kk + 0];
    float bdx = offset_b[2 * kk + 1];

    int   i00[4], i01[4], i10[4], i11[4];
    float w00[4], w01[4], w10[4], w11[4];

#pragma unroll
    for (int u = 0; u < 4; u++) {
        int n  = n0 + u;
        int y  = n >> 6;
        int xx = n & 63;
        float dy = bdy, dx = bdx;
#pragma unroll
        for (int p = 0; p < NCHK; p++) {
            const float* ob = g_offp + (((size_t)p * B_ + b) * OC18) * HW + n;
            dy += ob[(size_t)(2 * kk + 0) * HW];
            dx += ob[(size_t)(2 * kk + 1) * HW];
        }
        float sy = (float)(y - 1 + kk / 3) + dy;
        float sx = (float)(xx - 1 + kk % 3) + dx;
        float fy = floorf(sy), fx = floorf(sx);
        int y0 = (int)fy, x0 = (int)fx;
        int y1 = y0 + 1, x1 = x0 + 1;
        float wy = sy - fy, wx = sx - fx;
        bool vy0 = (unsigned)y0 < (unsigned)H_;
        bool vy1 = (unsigned)y1 < (unsigned)H_;
        bool vx0 = (unsigned)x0 < (unsigned)W_;
        bool vx1 = (unsigned)x1 < (unsigned)W_;
        int cy0 = min(max(y0, 0), H_ - 1), cy1 = min(max(y1, 0), H_ - 1);
        int cx0 = min(max(x0, 0), W_ - 1), cx1 = min(max(x1, 0), W_ - 1);
        i00[u] = cy0 * W_ + cx0;
        i01[u] = cy0 * W_ + cx1;
        i10[u] = cy1 * W_ + cx0;
        i11[u] = cy1 * W_ + cx1;
        w00[u] = (1.f - wy) * (1.f - wx) * (float)(vy0 && vx0);
        w01[u] = (1.f - wy) * wx         * (float)(vy0 && vx1);
        w10[u] = wy * (1.f - wx)         * (float)(vy1 && vx0);
        w11[u] = wy * wx                 * (float)(vy1 && vx1);
    }

    const float* xb = x + (size_t)b * CIN * HW;
    size_t base = ((size_t)b * KD + kk) * HW + n0;

    for (int c = 0; c < CIN; c++) {
        const float* xc = xb + (size_t)c * HW;
        size_t idx = base + (size_t)c * (KK9 * HW);
        uint2 hv, lv;
        unsigned short hs[4], ls[4];
#pragma unroll
        for (int u = 0; u < 4; u++) {
            float v = w00[u] * xc[i00[u]] + w01[u] * xc[i01[u]]
                    + w10[u] * xc[i10[u]] + w11[u] * xc[i11[u]];
            __nv_bfloat16 h = __float2bfloat16(v);
            float l = v - __bfloat162float(h);
            hs[u] = __bfloat16_as_ushort(h);
            ls[u] = __bfloat16_as_ushort(__float2bfloat16(l));
        }
        hv.x = ((uint32_t)hs[1] << 16) | hs[0];
        hv.y = ((uint32_t)hs[3] << 16) | hs[2];
        lv.x = ((uint32_t)ls[1] << 16) | ls[0];
        lv.y = ((uint32_t)ls[3] << 16) | ls[2];
        *(uint2*)(Phi + idx) = hv;
        *(uint2*)(Plo + idx) = lv;
    }
}

// ============================================================================
// Kernel B2: split dconv weights into bf16 hi/lo; also zero BN accumulators
// ============================================================================
__global__ void wsplit_kernel(const float* __restrict__ w,
                              __nv_bfloat16* __restrict__ hi,
                              __nv_bfloat16* __restrict__ lo) {
    int i = blockIdx.x * blockDim.x + threadIdx.x;
    if (i < COUT) { g_sum[i] = 0.f; g_sqs[i] = 0.f; }
    float v = w[i];
    __nv_bfloat16 h = __float2bfloat16(v);
    hi[i] = h;
    lo[i] = __float2bfloat16(v - __bfloat162float(h));
}

// ============================================================================
// Kernel C: HMMA GEMM  Y[b] = W[256,1152] @ P[b][1152,4096] + bias
// R10 winner: 8 warps, 64x32 warp tile, BK=32, 2-stage cp.async (loads before
// wait), register-lean pass order, __launch_bounds__(256,2) -> 2 CTAs/SM.
// ============================================================================
#define BK      32
#define NC      (KD / BK)        // 36
#define A_STR   40
#define B_STR   136
#define AH_OFF  0
#define AL_OFF  (128 * A_STR)
#define BH_OFF  (2 * 128 * A_STR)
#define BL_OFF  (BH_OFF + 32 * B_STR)
#define STG     (BL_OFF + 32 * B_STR)        // 18944 bf16 / stage
#define SMEM_GEMM (2 * STG * 2)              // 75776 bytes

__global__ void __launch_bounds__(256, 2)
gemm_mma_kernel(const __nv_bfloat16* __restrict__ Whi,
                const __nv_bfloat16* __restrict__ Wlo,
                const __nv_bfloat16* __restrict__ Phi,
                const __nv_bfloat16* __restrict__ Plo,
                const float* __restrict__ bias,
                float* __restrict__ Y) {
    extern __shared__ __nv_bfloat16 sm[];
    const uint32_t sbase = smem_u32(sm);

    int tid  = threadIdx.x;
    int wid  = tid >> 5;
    int lane = tid & 31;
    int bn = blockIdx.x * 128;
    int bm = blockIdx.y * 128;
    int b  = blockIdx.z;

    int wm = (wid >> 2) * 64;    // warp m offset
    int wn = (wid & 3) * 32;     // warp n offset

    const __nv_bfloat16* PbH = Phi + (size_t)b * KD * HW;
    const __nv_bfloat16* PbL = Plo + (size_t)b * KD * HW;

    float acc[4][4][4];
#pragma unroll
    for (int i = 0; i < 4; i++)
#pragma unroll
        for (int j = 0; j < 4; j++)
#pragma unroll
            for (int q = 0; q < 4; q++) acc[i][j][q] = 0.f;

    auto load_stage = [&](int chunk, int st) {
        int k0 = chunk * BK;
        uint32_t s0 = sbase + (uint32_t)(st * STG) * 2;
#pragma unroll
        for (int i = 0; i < 2; i++) {
            int idx = tid + i * 256;
            int m   = idx >> 2;
            int kq  = (idx & 3) << 3;
            size_t go = (size_t)(bm + m) * KD + k0 + kq;
            uint32_t sa = s0 + (uint32_t)(m * A_STR + kq) * 2;
            cpa16(sa + AH_OFF * 2, Whi + go);
            cpa16(sa + AL_OFF * 2, Wlo + go);
        }
#pragma unroll
        for (int i = 0; i < 2; i++) {
            int idx = tid + i * 256;
            int k   = idx >> 4;
            int nq  = (idx & 15) << 3;
            size_t go = (size_t)(k0 + k) * HW + bn + nq;
            uint32_t sa = s0 + (uint32_t)(k * B_STR + nq) * 2;
            cpa16(sa + BH_OFF * 2, PbH + go);
            cpa16(sa + BL_OFF * 2, PbL + go);
        }
        CPA_COMMIT();
    };

    load_stage(0, 0);

    int row  = lane & 15;
    int half = (lane >> 4) << 3;

    for (int c = 0; c < NC; c++) {
        int st = c & 1;
        if (c + 1 < NC) {
            load_stage(c + 1, st ^ 1);   // issue next-stage loads FIRST
            CPA_WAIT(1);
        } else {
            CPA_WAIT(0);
        }
        __syncthreads();

        uint32_t s0 = sbase + (uint32_t)(st * STG) * 2;

#pragma unroll
        for (int ks = 0; ks < BK; ks += 16) {
            // Pass order keeps ah/al disjoint in registers:
            //   load ah, bh, bl -> ah*bh, ah*bl -> load al -> al*bh
            uint32_t ah[4][4], bh[4][2], bl[4][2];
#pragma unroll
            for (int i = 0; i < 4; i++) {
                uint32_t a = s0 + (uint32_t)((wm + i * 16 + row) * A_STR + ks + half) * 2;
                ldsm4(ah[i], a + AH_OFF * 2);
            }
#pragma unroll
            for (int j = 0; j < 2; j++) {
                uint32_t a = s0 + (uint32_t)((ks + row) * B_STR + wn + j * 16 + half) * 2;
                uint32_t r0, r1, r2, r3;
                ldsm4t(r0, r1, r2, r3, a + BH_OFF * 2);
                bh[2 * j][0] = r0; bh[2 * j][1] = r1;
                bh[2 * j + 1][0] = r2; bh[2 * j + 1][1] = r3;
                ldsm4t(r0, r1, r2, r3, a + BL_OFF * 2);
                bl[2 * j][0] = r0; bl[2 * j][1] = r1;
                bl[2 * j + 1][0] = r2; bl[2 * j + 1][1] = r3;
            }
#pragma unroll
            for (int i = 0; i < 4; i++)
#pragma unroll
                for (int j = 0; j < 4; j++)
                    mma16816(acc[i][j], ah[i], bh[j]);
#pragma unroll
            for (int i = 0; i < 4; i++)
#pragma unroll
                for (int j = 0; j < 4; j++)
                    mma16816(acc[i][j], ah[i], bl[j]);

            uint32_t al[4][4];
#pragma unroll
            for (int i = 0; i < 4; i++) {
                uint32_t a = s0 + (uint32_t)((wm + i * 16 + row) * A_STR + ks + half) * 2;
                ldsm4(al[i], a + AL_OFF * 2);
            }
#pragma unroll
            for (int i = 0; i < 4; i++)
#pragma unroll
                for (int j = 0; j < 4; j++)
                    mma16816(acc[i][j], al[i], bh[j]);
        }
        __syncthreads();
    }

    // --- epilogue: add bias, write Y, fused BN partial sums ---
    int r  = lane >> 2;
    int c2 = (lane & 3) << 1;
#pragma unroll
    for (int i = 0; i < 4; i++) {
        int m0 = bm + wm + i * 16 + r;
        float b0 = bias[m0];
        float b1 = bias[m0 + 8];
        float* y0 = Y + ((size_t)b * COUT + m0) * HW + bn + wn + c2;
        float* y1 = y0 + (size_t)8 * HW;
        float sA = 0.f, qA = 0.f, sB = 0.f, qB = 0.f;
#pragma unroll
        for (int j = 0; j < 4; j++) {
            float v00 = acc[i][j][0] + b0, v01 = acc[i][j][1] + b0;
            float v10 = acc[i][j][2] + b1, v11 = acc[i][j][3] + b1;
            *(float2*)(y0 + j * 8) = make_float2(v00, v01);
            *(float2*)(y1 + j * 8) = make_float2(v10, v11);
            sA += v00 + v01; qA = fmaf(v00, v00, fmaf(v01, v01, qA));
            sB += v10 + v11; qB = fmaf(v10, v10, fmaf(v11, v11, qB));
        }
#pragma unroll
        for (int mk = 1; mk <= 2; mk <<= 1) {
            sA += __shfl_xor_sync(0xFFFFFFFF, sA, mk);
            qA += __shfl_xor_sync(0xFFFFFFFF, qA, mk);
            sB += __shfl_xor_sync(0xFFFFFFFF, sB, mk);
            qB += __shfl_xor_sync(0xFFFFFFFF, qB, mk);
        }
        if ((lane & 3) == 0) {
            atomicAdd(&g_sum[m0], sA);
            atomicAdd(&g_sqs[m0], qA);
            atomicAdd(&g_sum[m0 + 8], sB);
            atomicAdd(&g_sqs[m0 + 8], qB);
        }
    }
}

// ============================================================================
// Kernel D: finalize BN stats from accumulated sums
// ============================================================================
__global__ void bnfinal_kernel() {
    int o = threadIdx.x;
    const float invN = 1.f / (float)(B_ * HW);
    float m   = g_sum[o] * invN;
    float var = g_sqs[o] * invN - m * m;
    g_mean[o] = m;
    g_rstd[o] = rsqrtf(var + 1e-5f);
}

// ============================================================================
// Kernel E: normalize + affine + SiLU (in place, float4, fast exp)
// ============================================================================
__global__ void bnsilu_kernel(float* __restrict__ Y,
                              const float* __restrict__ gamma,
                              const float* __restrict__ beta) {
    size_t i4 = (size_t)blockIdx.x * blockDim.x + threadIdx.x;
    int o = (int)((i4 >> 10) & (COUT - 1));
    float m = g_mean[o], r = g_rstd[o], g = gamma[o], be = beta[o];
    float4 v = ((float4*)Y)[i4];
    float t;
    t = (v.x - m) * r * g + be; v.x = t / (1.f + __expf(-t));
    t = (v.y - m) * r * g + be; v.y = t / (1.f + __expf(-t));
    t = (v.z - m) * r * g + be; v.z = t / (1.f + __expf(-t));
    t = (v.w - m) * r * g + be; v.w = t / (1.f + __expf(-t));
    ((float4*)Y)[i4] = v;
}

// ============================================================================
// Launch
// ============================================================================
extern "C" void kernel_launch(void* const* d_in, const int* in_sizes, int n_in,
                              void* d_out, int out_size) {
    const float* x        = (const float*)d_in[0];
    const float* offset_w = (const float*)d_in[1];
    const float* offset_b = (const float*)d_in[2];
    const float* dconv_w  = (const float*)d_in[3];
    const float* dconv_b  = (const float*)d_in[4];
    const float* bn_gamma = (const float*)d_in[5];
    const float* bn_beta  = (const float*)d_in[6];
    float* out = (float*)d_out;

    __nv_bfloat16 *Phi, *Plo, *Whi, *Wlo;
    cudaGetSymbolAddress((void**)&Phi, g_Phi);
    cudaGetSymbolAddress((void**)&Plo, g_Plo);
    cudaGetSymbolAddress((void**)&Whi, g_Whi);
    cudaGetSymbolAddress((void**)&Wlo, g_Wlo);

    static bool attr_set = false;
    if (!attr_set) {
        cudaFuncSetAttribute(gemm_mma_kernel,
                             cudaFuncAttributeMaxDynamicSharedMemorySize,
                             SMEM_GEMM);
        attr_set = true;
    }

    // A: offset conv partials (smem-tiled x)
    offset_conv_part_kernel<<<dim3(256, NCHK), 128>>>(x, offset_w);

    // B2: split weights + zero BN accumulators
    wsplit_kernel<<<(COUT * KD) / 256, 256>>>(dconv_w, Whi, Wlo);

    // B: gather (4 pixels/thread, 8B stores)
    gather_kernel<<<(B_ * KK9 * HW / 4) / 256, 256>>>(x, offset_b, Phi, Plo);

    // C: HMMA GEMM + fused BN partial sums
    dim3 g(HW / 128, COUT / 128, B_);
    gemm_mma_kernel<<<g, 256, SMEM_GEMM>>>(Whi, Wlo, Phi, Plo, dconv_b, out);

    // D: finalize BN stats
    bnfinal_kernel<<<1, COUT>>>();

    // E: normalize + SiLU
    bnsilu_kernel<<<(B_ * COUT * HW / 4) / 256, 256>>>(out, bn_gamma, bn_beta);
}

// round 12
// speedup vs baseline: 1.1361x; 1.1361x over previous
#include <cuda_runtime.h>
#include <cuda_bf16.h>
#include <math.h>
#include <cstdint>

// Problem constants
#define B_    8
#define CIN   128
#define H_    64
#define W_    64
#define HW    (H_ * W_)        // 4096
#define COUT  256
#define KK9   9
#define OC18  18
#define KD    (CIN * KK9)      // 1152
#define NCHK  4                // offset-conv channel chunks
#define CCH   (CIN / NCHK)     // 32

// ---------------- scratch (device globals; no allocation allowed) -----------
__device__ float g_offp[NCHK * B_ * OC18 * HW];               // offset partials
__device__ __nv_bfloat16 g_Phi[(size_t)B_ * KD * HW];         // P hi [b][k][n]
__device__ __nv_bfloat16 g_Plo[(size_t)B_ * KD * HW];         // P lo
__device__ __nv_bfloat16 g_Whi[COUT * KD];                    // W hi [m][k]
__device__ __nv_bfloat16 g_Wlo[COUT * KD];
__device__ float g_sum[COUT];
__device__ float g_sqs[COUT];
__device__ float g_mean[COUT];
__device__ float g_rstd[COUT];

// ============================================================================
// PTX helpers (plain sm_80+ instructions — compile for compute_103)
// ============================================================================
__device__ __forceinline__ uint32_t smem_u32(const void* p) {
    uint32_t a;
    asm("{ .reg .u64 t; cvta.to.shared.u64 t, %1; cvt.u32.u64 %0, t; }"
        : "=r"(a) : "l"(p));
    return a;
}
__device__ __forceinline__ void cpa16(uint32_t s, const void* g) {
    asm volatile("cp.async.cg.shared.global [%0], [%1], 16;" :: "r"(s), "l"(g));
}
#define CPA_COMMIT() asm volatile("cp.async.commit_group;" ::: "memory")
#define CPA_WAIT(N)  asm volatile("cp.async.wait_group %0;" :: "n"(N) : "memory")

__device__ __forceinline__ void ldsm4(uint32_t* r, uint32_t a) {
    asm volatile("ldmatrix.sync.aligned.m8n8.x4.shared.b16 {%0,%1,%2,%3}, [%4];"
                 : "=r"(r[0]), "=r"(r[1]), "=r"(r[2]), "=r"(r[3]) : "r"(a));
}
__device__ __forceinline__ void ldsm4t(uint32_t& r0, uint32_t& r1,
                                       uint32_t& r2, uint32_t& r3, uint32_t a) {
    asm volatile("ldmatrix.sync.aligned.m8n8.x4.trans.shared.b16 {%0,%1,%2,%3}, [%4];"
                 : "=r"(r0), "=r"(r1), "=r"(r2), "=r"(r3) : "r"(a));
}
__device__ __forceinline__ void mma16816(float* d, const uint32_t* a,
                                         const uint32_t* b) {
    asm volatile(
        "mma.sync.aligned.m16n8k16.row.col.f32.bf16.bf16.f32 "
        "{%0,%1,%2,%3}, {%4,%5,%6,%7}, {%8,%9}, {%0,%1,%2,%3};"
        : "+f"(d[0]), "+f"(d[1]), "+f"(d[2]), "+f"(d[3])
        : "r"(a[0]), "r"(a[1]), "r"(a[2]), "r"(a[3]), "r"(b[0]), "r"(b[1]));
}

// ============================================================================
// Kernel A: offset conv partials (4 channel chunks) — R10 version
// ============================================================================
__global__ void offset_conv_part_kernel(const float* __restrict__ x,
                                        const float* __restrict__ w) {
    __shared__ float ws[OC18 * CCH * 9];
    int cc = blockIdx.y;
    for (int i = threadIdx.x; i < OC18 * CCH * 9; i += blockDim.x) {
        int oc = i / (CCH * 9);
        int r  = i - oc * (CCH * 9);
        ws[i] = w[oc * KD + cc * (CCH * 9) + r];
    }
    __syncthreads();

    int gid = blockIdx.x * blockDim.x + threadIdx.x;
    int b   = gid >> 12;
    int pix = gid & 4095;
    int y   = pix >> 6;
    int xx  = pix & 63;

    float acc[OC18];
#pragma unroll
    for (int oc = 0; oc < OC18; oc++) acc[oc] = 0.f;

    const float* xb = x + (size_t)b * CIN * HW + (size_t)cc * CCH * HW;
    for (int c = 0; c < CCH; c++) {
        const float* xc = xb + (size_t)c * HW;
        float v[9];
#pragma unroll
        for (int ky = 0; ky < 3; ky++) {
            int yy = y - 1 + ky;
            bool yv = (unsigned)yy < (unsigned)H_;
#pragma unroll
            for (int kx = 0; kx < 3; kx++) {
                int x2 = xx - 1 + kx;
                bool xv = (unsigned)x2 < (unsigned)W_;
                v[ky * 3 + kx] = (yv && xv) ? xc[yy * W_ + x2] : 0.f;
            }
        }
#pragma unroll
        for (int kk = 0; kk < 9; kk++) {
            float xvv = v[kk];
#pragma unroll
            for (int oc = 0; oc < OC18; oc++)
                acc[oc] = fmaf(xvv, ws[oc * (CCH * 9) + c * 9 + kk], acc[oc]);
        }
    }

    float* ob = g_offp + (((size_t)cc * B_ + b) * OC18) * HW + pix;
#pragma unroll
    for (int oc = 0; oc < OC18; oc++) ob[(size_t)oc * HW] = acc[oc];
}

// ============================================================================
// Kernel B: deformable bilinear gather, 2 pixels/thread -> bf16x2 stores
// (R10 version; channel loop unroll raised 2 -> 4 for deeper MLP)
// ============================================================================
__global__ void gather_kernel(const float* __restrict__ x,
                              const float* __restrict__ offset_b,
                              __nv_bfloat16* __restrict__ Phi,
                              __nv_bfloat16* __restrict__ Plo) {
    int gid = blockIdx.x * blockDim.x + threadIdx.x;    // < 147456
    int p2  = gid & 2047;           // pixel pair
    int t   = gid >> 11;            // b*9 + kk
    int kk  = t % 9;
    int b   = t / 9;
    int n0  = p2 * 2;

    float bdy = offset_b[2 * kk + 0];
    float bdx = offset_b[2 * kk + 1];

    int   i00[2], i01[2], i10[2], i11[2];
    float w00[2], w01[2], w10[2], w11[2];

#pragma unroll
    for (int u = 0; u < 2; u++) {
        int n  = n0 + u;
        int y  = n >> 6;
        int xx = n & 63;
        float dy = bdy, dx = bdx;
#pragma unroll
        for (int p = 0; p < NCHK; p++) {
            const float* ob = g_offp + (((size_t)p * B_ + b) * OC18) * HW + n;
            dy += ob[(size_t)(2 * kk + 0) * HW];
            dx += ob[(size_t)(2 * kk + 1) * HW];
        }
        float sy = (float)(y - 1 + kk / 3) + dy;
        float sx = (float)(xx - 1 + kk % 3) + dx;
        float fy = floorf(sy), fx = floorf(sx);
        int y0 = (int)fy, x0 = (int)fx;
        int y1 = y0 + 1, x1 = x0 + 1;
        float wy = sy - fy, wx = sx - fx;
        bool vy0 = (unsigned)y0 < (unsigned)H_;
        bool vy1 = (unsigned)y1 < (unsigned)H_;
        bool vx0 = (unsigned)x0 < (unsigned)W_;
        bool vx1 = (unsigned)x1 < (unsigned)W_;
        int cy0 = min(max(y0, 0), H_ - 1), cy1 = min(max(y1, 0), H_ - 1);
        int cx0 = min(max(x0, 0), W_ - 1), cx1 = min(max(x1, 0), W_ - 1);
        i00[u] = cy0 * W_ + cx0;
        i01[u] = cy0 * W_ + cx1;
        i10[u] = cy1 * W_ + cx0;
        i11[u] = cy1 * W_ + cx1;
        w00[u] = (1.f - wy) * (1.f - wx) * (float)(vy0 && vx0);
        w01[u] = (1.f - wy) * wx         * (float)(vy0 && vx1);
        w10[u] = wy * (1.f - wx)         * (float)(vy1 && vx0);
        w11[u] = wy * wx                 * (float)(vy1 && vx1);
    }

    const float* xb = x + (size_t)b * CIN * HW;
    size_t base = ((size_t)b * KD + kk) * HW + n0;

#pragma unroll 4
    for (int c = 0; c < CIN; c++) {
        const float* xc = xb + (size_t)c * HW;
        size_t idx = base + (size_t)c * (KK9 * HW);
        float v0 = w00[0] * xc[i00[0]] + w01[0] * xc[i01[0]]
                 + w10[0] * xc[i10[0]] + w11[0] * xc[i11[0]];
        float v1 = w00[1] * xc[i00[1]] + w01[1] * xc[i01[1]]
                 + w10[1] * xc[i10[1]] + w11[1] * xc[i11[1]];
        __nv_bfloat16 h0 = __float2bfloat16(v0);
        __nv_bfloat16 h1 = __float2bfloat16(v1);
        float l0 = v0 - __bfloat162float(h0);
        float l1 = v1 - __bfloat162float(h1);
        *(__nv_bfloat162*)(Phi + idx) = __nv_bfloat162(h0, h1);
        *(__nv_bfloat162*)(Plo + idx) =
            __nv_bfloat162(__float2bfloat16(l0), __float2bfloat16(l1));
    }
}

// ============================================================================
// Kernel B2: split dconv weights into bf16 hi/lo; also zero BN accumulators
// ============================================================================
__global__ void wsplit_kernel(const float* __restrict__ w,
                              __nv_bfloat16* __restrict__ hi,
                              __nv_bfloat16* __restrict__ lo) {
    int i = blockIdx.x * blockDim.x + threadIdx.x;
    if (i < COUT) { g_sum[i] = 0.f; g_sqs[i] = 0.f; }
    float v = w[i];
    __nv_bfloat16 h = __float2bfloat16(v);
    hi[i] = h;
    lo[i] = __float2bfloat16(v - __bfloat162float(h));
}

// ============================================================================
// Kernel C: HMMA GEMM  Y[b] = W[256,1152] @ P[b][1152,4096] + bias
// R10 winner: 8 warps, 64x32 warp tile, BK=32, 2-stage cp.async (loads before
// wait), register-lean pass order, __launch_bounds__(256,2) -> 2 CTAs/SM.
// ============================================================================
#define BK      32
#define NC      (KD / BK)        // 36
#define A_STR   40
#define B_STR   136
#define AH_OFF  0
#define AL_OFF  (128 * A_STR)
#define BH_OFF  (2 * 128 * A_STR)
#define BL_OFF  (BH_OFF + 32 * B_STR)
#define STG     (BL_OFF + 32 * B_STR)        // 18944 bf16 / stage
#define SMEM_GEMM (2 * STG * 2)              // 75776 bytes

__global__ void __launch_bounds__(256, 2)
gemm_mma_kernel(const __nv_bfloat16* __restrict__ Whi,
                const __nv_bfloat16* __restrict__ Wlo,
                const __nv_bfloat16* __restrict__ Phi,
                const __nv_bfloat16* __restrict__ Plo,
                const float* __restrict__ bias,
                float* __restrict__ Y) {
    extern __shared__ __nv_bfloat16 sm[];
    const uint32_t sbase = smem_u32(sm);

    int tid  = threadIdx.x;
    int wid  = tid >> 5;
    int lane = tid & 31;
    int bn = blockIdx.x * 128;
    int bm = blockIdx.y * 128;
    int b  = blockIdx.z;

    int wm = (wid >> 2) * 64;    // warp m offset
    int wn = (wid & 3) * 32;     // warp n offset

    const __nv_bfloat16* PbH = Phi + (size_t)b * KD * HW;
    const __nv_bfloat16* PbL = Plo + (size_t)b * KD * HW;

    float acc[4][4][4];
#pragma unroll
    for (int i = 0; i < 4; i++)
#pragma unroll
        for (int j = 0; j < 4; j++)
#pragma unroll
            for (int q = 0; q < 4; q++) acc[i][j][q] = 0.f;

    auto load_stage = [&](int chunk, int st) {
        int k0 = chunk * BK;
        uint32_t s0 = sbase + (uint32_t)(st * STG) * 2;
#pragma unroll
        for (int i = 0; i < 2; i++) {
            int idx = tid + i * 256;
            int m   = idx >> 2;
            int kq  = (idx & 3) << 3;
            size_t go = (size_t)(bm + m) * KD + k0 + kq;
            uint32_t sa = s0 + (uint32_t)(m * A_STR + kq) * 2;
            cpa16(sa + AH_OFF * 2, Whi + go);
            cpa16(sa + AL_OFF * 2, Wlo + go);
        }
#pragma unroll
        for (int i = 0; i < 2; i++) {
            int idx = tid + i * 256;
            int k   = idx >> 4;
            int nq  = (idx & 15) << 3;
            size_t go = (size_t)(k0 + k) * HW + bn + nq;
            uint32_t sa = s0 + (uint32_t)(k * B_STR + nq) * 2;
            cpa16(sa + BH_OFF * 2, PbH + go);
            cpa16(sa + BL_OFF * 2, PbL + go);
        }
        CPA_COMMIT();
    };

    load_stage(0, 0);

    int row  = lane & 15;
    int half = (lane >> 4) << 3;

    for (int c = 0; c < NC; c++) {
        int st = c & 1;
        if (c + 1 < NC) {
            load_stage(c + 1, st ^ 1);   // issue next-stage loads FIRST
            CPA_WAIT(1);
        } else {
            CPA_WAIT(0);
        }
        __syncthreads();

        uint32_t s0 = sbase + (uint32_t)(st * STG) * 2;

#pragma unroll
        for (int ks = 0; ks < BK; ks += 16) {
            // Pass order keeps ah/al disjoint in registers:
            //   load ah, bh, bl -> ah*bh, ah*bl -> load al -> al*bh
            uint32_t ah[4][4], bh[4][2], bl[4][2];
#pragma unroll
            for (int i = 0; i < 4; i++) {
                uint32_t a = s0 + (uint32_t)((wm + i * 16 + row) * A_STR + ks + half) * 2;
                ldsm4(ah[i], a + AH_OFF * 2);
            }
#pragma unroll
            for (int j = 0; j < 2; j++) {
                uint32_t a = s0 + (uint32_t)((ks + row) * B_STR + wn + j * 16 + half) * 2;
                uint32_t r0, r1, r2, r3;
                ldsm4t(r0, r1, r2, r3, a + BH_OFF * 2);
                bh[2 * j][0] = r0; bh[2 * j][1] = r1;
                bh[2 * j + 1][0] = r2; bh[2 * j + 1][1] = r3;
                ldsm4t(r0, r1, r2, r3, a + BL_OFF * 2);
                bl[2 * j][0] = r0; bl[2 * j][1] = r1;
                bl[2 * j + 1][0] = r2; bl[2 * j + 1][1] = r3;
            }
#pragma unroll
            for (int i = 0; i < 4; i++)
#pragma unroll
                for (int j = 0; j < 4; j++)
                    mma16816(acc[i][j], ah[i], bh[j]);
#pragma unroll
            for (int i = 0; i < 4; i++)
#pragma unroll
                for (int j = 0; j < 4; j++)
                    mma16816(acc[i][j], ah[i], bl[j]);

            uint32_t al[4][4];
#pragma unroll
            for (int i = 0; i < 4; i++) {
                uint32_t a = s0 + (uint32_t)((wm + i * 16 + row) * A_STR + ks + half) * 2;
                ldsm4(al[i], a + AL_OFF * 2);
            }
#pragma unroll
            for (int i = 0; i < 4; i++)
#pragma unroll
                for (int j = 0; j < 4; j++)
                    mma16816(acc[i][j], al[i], bh[j]);
        }
        __syncthreads();
    }

    // --- epilogue: add bias, write Y, fused BN partial sums ---
    int r  = lane >> 2;
    int c2 = (lane & 3) << 1;
#pragma unroll
    for (int i = 0; i < 4; i++) {
        int m0 = bm + wm + i * 16 + r;
        float b0 = bias[m0];
        float b1 = bias[m0 + 8];
        float* y0 = Y + ((size_t)b * COUT + m0) * HW + bn + wn + c2;
        float* y1 = y0 + (size_t)8 * HW;
        float sA = 0.f, qA = 0.f, sB = 0.f, qB = 0.f;
#pragma unroll
        for (int j = 0; j < 4; j++) {
            float v00 = acc[i][j][0] + b0, v01 = acc[i][j][1] + b0;
            float v10 = acc[i][j][2] + b1, v11 = acc[i][j][3] + b1;
            *(float2*)(y0 + j * 8) = make_float2(v00, v01);
            *(float2*)(y1 + j * 8) = make_float2(v10, v11);
            sA += v00 + v01; qA = fmaf(v00, v00, fmaf(v01, v01, qA));
            sB += v10 + v11; qB = fmaf(v10, v10, fmaf(v11, v11, qB));
        }
#pragma unroll
        for (int mk = 1; mk <= 2; mk <<= 1) {
            sA += __shfl_xor_sync(0xFFFFFFFF, sA, mk);
            qA += __shfl_xor_sync(0xFFFFFFFF, qA, mk);
            sB += __shfl_xor_sync(0xFFFFFFFF, sB, mk);
            qB += __shfl_xor_sync(0xFFFFFFFF, qB, mk);
        }
        if ((lane & 3) == 0) {
            atomicAdd(&g_sum[m0], sA);
            atomicAdd(&g_sqs[m0], qA);
            atomicAdd(&g_sum[m0 + 8], sB);
            atomicAdd(&g_sqs[m0 + 8], qB);
        }
    }
}

// ============================================================================
// Kernel D: finalize BN stats from accumulated sums
// ============================================================================
__global__ void bnfinal_kernel() {
    int o = threadIdx.x;
    const float invN = 1.f / (float)(B_ * HW);
    float m   = g_sum[o] * invN;
    float var = g_sqs[o] * invN - m * m;
    g_mean[o] = m;
    g_rstd[o] = rsqrtf(var + 1e-5f);
}

// ============================================================================
// Kernel E: normalize + affine + SiLU (in place, float4, fast exp)
// ============================================================================
__global__ void bnsilu_kernel(float* __restrict__ Y,
                              const float* __restrict__ gamma,
                              const float* __restrict__ beta) {
    size_t i4 = (size_t)blockIdx.x * blockDim.x + threadIdx.x;
    int o = (int)((i4 >> 10) & (COUT - 1));
    float m = g_mean[o], r = g_rstd[o], g = gamma[o], be = beta[o];
    float4 v = ((float4*)Y)[i4];
    float t;
    t = (v.x - m) * r * g + be; v.x = t / (1.f + __expf(-t));
    t = (v.y - m) * r * g + be; v.y = t / (1.f + __expf(-t));
    t = (v.z - m) * r * g + be; v.z = t / (1.f + __expf(-t));
    t = (v.w - m) * r * g + be; v.w = t / (1.f + __expf(-t));
    ((float4*)Y)[i4] = v;
}

// ============================================================================
// Launch
// ============================================================================
extern "C" void kernel_launch(void* const* d_in, const int* in_sizes, int n_in,
                              void* d_out, int out_size) {
    const float* x        = (const float*)d_in[0];
    const float* offset_w = (const float*)d_in[1];
    const float* offset_b = (const float*)d_in[2];
    const float* dconv_w  = (const float*)d_in[3];
    const float* dconv_b  = (const float*)d_in[4];
    const float* bn_gamma = (const float*)d_in[5];
    const float* bn_beta  = (const float*)d_in[6];
    float* out = (float*)d_out;

    __nv_bfloat16 *Phi, *Plo, *Whi, *Wlo;
    cudaGetSymbolAddress((void**)&Phi, g_Phi);
    cudaGetSymbolAddress((void**)&Plo, g_Plo);
    cudaGetSymbolAddress((void**)&Whi, g_Whi);
    cudaGetSymbolAddress((void**)&Wlo, g_Wlo);

    static bool attr_set = false;
    if (!attr_set) {
        cudaFuncSetAttribute(gemm_mma_kernel,
                             cudaFuncAttributeMaxDynamicSharedMemorySize,
                             SMEM_GEMM);
        attr_set = true;
    }

    // A: offset conv partials
    offset_conv_part_kernel<<<dim3(256, NCHK), 128>>>(x, offset_w);

    // B2: split weights + zero BN accumulators
    wsplit_kernel<<<(COUT * KD) / 256, 256>>>(dconv_w, Whi, Wlo);

    // B: gather (2 pixels/thread, unroll 4)
    gather_kernel<<<(B_ * KK9 * HW / 2) / 256, 256>>>(x, offset_b, Phi, Plo);

    // C: HMMA GEMM + fused BN partial sums
    dim3 g(HW / 128, COUT / 128, B_);
    gemm_mma_kernel<<<g, 256, SMEM_GEMM>>>(Whi, Wlo, Phi, Plo, dconv_b, out);

    // D: finalize BN stats
    bnfinal_kernel<<<1, COUT>>>();

    // E: normalize + SiLU
    bnsilu_kernel<<<(B_ * COUT * HW / 4) / 256, 256>>>(out, bn_gamma, bn_beta);
}

// round 13
// speedup vs baseline: 1.3493x; 1.1876x over previous
#include <cuda_runtime.h>
#include <cuda_fp16.h>
#include <cuda_bf16.h>
#include <math.h>
#include <cstdint>

// Problem constants
#define B_    8
#define CIN   128
#define H_    64
#define W_    64
#define HW    (H_ * W_)        // 4096
#define COUT  256
#define KK9   9
#define OC18  18
#define KD    (CIN * KK9)      // 1152
#define NCHK  4                // offset-conv channel chunks
#define CCH   (CIN / NCHK)     // 32

// ---------------- scratch (device globals; no allocation allowed) -----------
__device__ float g_offp[NCHK * B_ * OC18 * HW];               // offset partials
__device__ __half g_Ph[(size_t)B_ * KD * HW];                 // P fp16 [b][k][n]
__device__ __half g_Whi[COUT * KD];                           // W hi fp16 [m][k]
__device__ __half g_Wlo[COUT * KD];                           // W lo fp16
__device__ float g_sum[COUT];
__device__ float g_sqs[COUT];
__device__ float g_mean[COUT];
__device__ float g_rstd[COUT];

// ============================================================================
// PTX helpers (plain sm_80+ instructions — compile for compute_103)
// ============================================================================
__device__ __forceinline__ uint32_t smem_u32(const void* p) {
    uint32_t a;
    asm("{ .reg .u64 t; cvta.to.shared.u64 t, %1; cvt.u32.u64 %0, t; }"
        : "=r"(a) : "l"(p));
    return a;
}
__device__ __forceinline__ void cpa16(uint32_t s, const void* g) {
    asm volatile("cp.async.cg.shared.global [%0], [%1], 16;" :: "r"(s), "l"(g));
}
#define CPA_COMMIT() asm volatile("cp.async.commit_group;" ::: "memory")
#define CPA_WAIT(N)  asm volatile("cp.async.wait_group %0;" :: "n"(N) : "memory")

__device__ __forceinline__ void ldsm4(uint32_t* r, uint32_t a) {
    asm volatile("ldmatrix.sync.aligned.m8n8.x4.shared.b16 {%0,%1,%2,%3}, [%4];"
                 : "=r"(r[0]), "=r"(r[1]), "=r"(r[2]), "=r"(r[3]) : "r"(a));
}
__device__ __forceinline__ void ldsm4t(uint32_t& r0, uint32_t& r1,
                                       uint32_t& r2, uint32_t& r3, uint32_t a) {
    asm volatile("ldmatrix.sync.aligned.m8n8.x4.trans.shared.b16 {%0,%1,%2,%3}, [%4];"
                 : "=r"(r0), "=r"(r1), "=r"(r2), "=r"(r3) : "r"(a));
}
// fp16 HMMA, fp32 accumulate
__device__ __forceinline__ void mma16816(float* d, const uint32_t* a,
                                         const uint32_t* b) {
    asm volatile(
        "mma.sync.aligned.m16n8k16.row.col.f32.f16.f16.f32 "
        "{%0,%1,%2,%3}, {%4,%5,%6,%7}, {%8,%9}, {%0,%1,%2,%3};"
        : "+f"(d[0]), "+f"(d[1]), "+f"(d[2]), "+f"(d[3])
        : "r"(a[0]), "r"(a[1]), "r"(a[2]), "r"(a[3]), "r"(b[0]), "r"(b[1]));
}

// ============================================================================
// Kernel A: offset conv partials (4 channel chunks) — R10 version, unchanged
// ============================================================================
__global__ void offset_conv_part_kernel(const float* __restrict__ x,
                                        const float* __restrict__ w) {
    __shared__ float ws[OC18 * CCH * 9];
    int cc = blockIdx.y;
    for (int i = threadIdx.x; i < OC18 * CCH * 9; i += blockDim.x) {
        int oc = i / (CCH * 9);
        int r  = i - oc * (CCH * 9);
        ws[i] = w[oc * KD + cc * (CCH * 9) + r];
    }
    __syncthreads();

    int gid = blockIdx.x * blockDim.x + threadIdx.x;
    int b   = gid >> 12;
    int pix = gid & 4095;
    int y   = pix >> 6;
    int xx  = pix & 63;

    float acc[OC18];
#pragma unroll
    for (int oc = 0; oc < OC18; oc++) acc[oc] = 0.f;

    const float* xb = x + (size_t)b * CIN * HW + (size_t)cc * CCH * HW;
    for (int c = 0; c < CCH; c++) {
        const float* xc = xb + (size_t)c * HW;
        float v[9];
#pragma unroll
        for (int ky = 0; ky < 3; ky++) {
            int yy = y - 1 + ky;
            bool yv = (unsigned)yy < (unsigned)H_;
#pragma unroll
            for (int kx = 0; kx < 3; kx++) {
                int x2 = xx - 1 + kx;
                bool xv = (unsigned)x2 < (unsigned)W_;
                v[ky * 3 + kx] = (yv && xv) ? xc[yy * W_ + x2] : 0.f;
            }
        }
#pragma unroll
        for (int kk = 0; kk < 9; kk++) {
            float xvv = v[kk];
#pragma unroll
            for (int oc = 0; oc < OC18; oc++)
                acc[oc] = fmaf(xvv, ws[oc * (CCH * 9) + c * 9 + kk], acc[oc]);
        }
    }

    float* ob = g_offp + (((size_t)cc * B_ + b) * OC18) * HW + pix;
#pragma unroll
    for (int oc = 0; oc < OC18; oc++) ob[(size_t)oc * HW] = acc[oc];
}

// ============================================================================
// Kernel B: deformable bilinear gather, 2 pixels/thread -> single fp16 P
// ============================================================================
__global__ void gather_kernel(const float* __restrict__ x,
                              const float* __restrict__ offset_b,
                              __half* __restrict__ Ph) {
    int gid = blockIdx.x * blockDim.x + threadIdx.x;    // < 147456
    int p2  = gid & 2047;           // pixel pair
    int t   = gid >> 11;            // b*9 + kk
    int kk  = t % 9;
    int b   = t / 9;
    int n0  = p2 * 2;

    float bdy = offset_b[2 * kk + 0];
    float bdx = offset_b[2 * kk + 1];

    int   i00[2], i01[2], i10[2], i11[2];
    float w00[2], w01[2], w10[2], w11[2];

#pragma unroll
    for (int u = 0; u < 2; u++) {
        int n  = n0 + u;
        int y  = n >> 6;
        int xx = n & 63;
        float dy = bdy, dx = bdx;
#pragma unroll
        for (int p = 0; p < NCHK; p++) {
            const float* ob = g_offp + (((size_t)p * B_ + b) * OC18) * HW + n;
            dy += ob[(size_t)(2 * kk + 0) * HW];
            dx += ob[(size_t)(2 * kk + 1) * HW];
        }
        float sy = (float)(y - 1 + kk / 3) + dy;
        float sx = (float)(xx - 1 + kk % 3) + dx;
        float fy = floorf(sy), fx = floorf(sx);
        int y0 = (int)fy, x0 = (int)fx;
        int y1 = y0 + 1, x1 = x0 + 1;
        float wy = sy - fy, wx = sx - fx;
        bool vy0 = (unsigned)y0 < (unsigned)H_;
        bool vy1 = (unsigned)y1 < (unsigned)H_;
        bool vx0 = (unsigned)x0 < (unsigned)W_;
        bool vx1 = (unsigned)x1 < (unsigned)W_;
        int cy0 = min(max(y0, 0), H_ - 1), cy1 = min(max(y1, 0), H_ - 1);
        int cx0 = min(max(x0, 0), W_ - 1), cx1 = min(max(x1, 0), W_ - 1);
        i00[u] = cy0 * W_ + cx0;
        i01[u] = cy0 * W_ + cx1;
        i10[u] = cy1 * W_ + cx0;
        i11[u] = cy1 * W_ + cx1;
        w00[u] = (1.f - wy) * (1.f - wx) * (float)(vy0 && vx0);
        w01[u] = (1.f - wy) * wx         * (float)(vy0 && vx1);
        w10[u] = wy * (1.f - wx)         * (float)(vy1 && vx0);
        w11[u] = wy * wx                 * (float)(vy1 && vx1);
    }

    const float* xb = x + (size_t)b * CIN * HW;
    size_t base = ((size_t)b * KD + kk) * HW + n0;

#pragma unroll 2
    for (int c = 0; c < CIN; c++) {
        const float* xc = xb + (size_t)c * HW;
        size_t idx = base + (size_t)c * (KK9 * HW);
        float v0 = w00[0] * xc[i00[0]] + w01[0] * xc[i01[0]]
                 + w10[0] * xc[i10[0]] + w11[0] * xc[i11[0]];
        float v1 = w00[1] * xc[i00[1]] + w01[1] * xc[i01[1]]
                 + w10[1] * xc[i10[1]] + w11[1] * xc[i11[1]];
        *(__half2*)(Ph + idx) = __floats2half2_rn(v0, v1);
    }
}

// ============================================================================
// Kernel B2: split dconv weights into fp16 hi/lo; also zero BN accumulators
// ============================================================================
__global__ void wsplit_kernel(const float* __restrict__ w,
                              __half* __restrict__ hi,
                              __half* __restrict__ lo) {
    int i = blockIdx.x * blockDim.x + threadIdx.x;
    if (i < COUT) { g_sum[i] = 0.f; g_sqs[i] = 0.f; }
    float v = w[i];
    __half h = __float2half_rn(v);
    hi[i] = h;
    lo[i] = __float2half_rn(v - __half2float(h));
}

// ============================================================================
// Kernel C: HMMA GEMM  Y[b] = W[256,1152] @ P[b][1152,4096] + bias
// fp16 2-pass (Wh*P + Wl*P), fp32 accum. R10 pipeline: 8 warps, 64x32 warp
// tile, BK=32, 2-stage cp.async (loads before wait), launch_bounds(256,2).
// Fused BN partial sums via shuffle + atomics in the epilogue.
// ============================================================================
#define BK      32
#define NC      (KD / BK)        // 36
#define A_STR   40
#define B_STR   136
#define AH_OFF  0
#define AL_OFF  (128 * A_STR)                // 5120
#define BH_OFF  (2 * 128 * A_STR)            // 10240
#define STG     (BH_OFF + 32 * B_STR)        // 14592 halves / stage
#define SMEM_GEMM (2 * STG * 2)              // 58368 bytes

__global__ void __launch_bounds__(256, 2)
gemm_mma_kernel(const __half* __restrict__ Whi,
                const __half* __restrict__ Wlo,
                const __half* __restrict__ Ph,
                const float* __restrict__ bias,
                float* __restrict__ Y) {
    extern __shared__ __half sm[];
    const uint32_t sbase = smem_u32(sm);

    int tid  = threadIdx.x;
    int wid  = tid >> 5;
    int lane = tid & 31;
    int bn = blockIdx.x * 128;
    int bm = blockIdx.y * 128;
    int b  = blockIdx.z;

    int wm = (wid >> 2) * 64;    // warp m offset
    int wn = (wid & 3) * 32;     // warp n offset

    const __half* Pb = Ph + (size_t)b * KD * HW;

    float acc[4][4][4];
#pragma unroll
    for (int i = 0; i < 4; i++)
#pragma unroll
        for (int j = 0; j < 4; j++)
#pragma unroll
            for (int q = 0; q < 4; q++) acc[i][j][q] = 0.f;

    auto load_stage = [&](int chunk, int st) {
        int k0 = chunk * BK;
        uint32_t s0 = sbase + (uint32_t)(st * STG) * 2;
#pragma unroll
        for (int i = 0; i < 2; i++) {
            int idx = tid + i * 256;
            int m   = idx >> 2;
            int kq  = (idx & 3) << 3;
            size_t go = (size_t)(bm + m) * KD + k0 + kq;
            uint32_t sa = s0 + (uint32_t)(m * A_STR + kq) * 2;
            cpa16(sa + AH_OFF * 2, Whi + go);
            cpa16(sa + AL_OFF * 2, Wlo + go);
        }
#pragma unroll
        for (int i = 0; i < 2; i++) {
            int idx = tid + i * 256;
            int k   = idx >> 4;
            int nq  = (idx & 15) << 3;
            size_t go = (size_t)(k0 + k) * HW + bn + nq;
            uint32_t sa = s0 + (uint32_t)(k * B_STR + nq) * 2;
            cpa16(sa + BH_OFF * 2, Pb + go);
        }
        CPA_COMMIT();
    };

    load_stage(0, 0);

    int row  = lane & 15;
    int half = (lane >> 4) << 3;

    for (int c = 0; c < NC; c++) {
        int st = c & 1;
        if (c + 1 < NC) {
            load_stage(c + 1, st ^ 1);   // issue next-stage loads FIRST
            CPA_WAIT(1);
        } else {
            CPA_WAIT(0);
        }
        __syncthreads();

        uint32_t s0 = sbase + (uint32_t)(st * STG) * 2;

#pragma unroll
        for (int ks = 0; ks < BK; ks += 16) {
            // load ah, bh -> ah*bh -> load al -> al*bh (ah/al disjoint in regs)
            uint32_t ah[4][4], bh[4][2];
#pragma unroll
            for (int i = 0; i < 4; i++) {
                uint32_t a = s0 + (uint32_t)((wm + i * 16 + row) * A_STR + ks + half) * 2;
                ldsm4(ah[i], a + AH_OFF * 2);
            }
#pragma unroll
            for (int j = 0; j < 2; j++) {
                uint32_t a = s0 + (uint32_t)((ks + row) * B_STR + wn + j * 16 + half) * 2;
                uint32_t r0, r1, r2, r3;
                ldsm4t(r0, r1, r2, r3, a + BH_OFF * 2);
                bh[2 * j][0] = r0; bh[2 * j][1] = r1;
                bh[2 * j + 1][0] = r2; bh[2 * j + 1][1] = r3;
            }
#pragma unroll
            for (int i = 0; i < 4; i++)
#pragma unroll
                for (int j = 0; j < 4; j++)
                    mma16816(acc[i][j], ah[i], bh[j]);

            uint32_t al[4][4];
#pragma unroll
            for (int i = 0; i < 4; i++) {
                uint32_t a = s0 + (uint32_t)((wm + i * 16 + row) * A_STR + ks + half) * 2;
                ldsm4(al[i], a + AL_OFF * 2);
            }
#pragma unroll
            for (int i = 0; i < 4; i++)
#pragma unroll
                for (int j = 0; j < 4; j++)
                    mma16816(acc[i][j], al[i], bh[j]);
        }
        __syncthreads();
    }

    // --- epilogue: add bias, write Y, fused BN partial sums ---
    int r  = lane >> 2;
    int c2 = (lane & 3) << 1;
#pragma unroll
    for (int i = 0; i < 4; i++) {
        int m0 = bm + wm + i * 16 + r;
        float b0 = bias[m0];
        float b1 = bias[m0 + 8];
        float* y0 = Y + ((size_t)b * COUT + m0) * HW + bn + wn + c2;
        float* y1 = y0 + (size_t)8 * HW;
        float sA = 0.f, qA = 0.f, sB = 0.f, qB = 0.f;
#pragma unroll
        for (int j = 0; j < 4; j++) {
            float v00 = acc[i][j][0] + b0, v01 = acc[i][j][1] + b0;
            float v10 = acc[i][j][2] + b1, v11 = acc[i][j][3] + b1;
            *(float2*)(y0 + j * 8) = make_float2(v00, v01);
            *(float2*)(y1 + j * 8) = make_float2(v10, v11);
            sA += v00 + v01; qA = fmaf(v00, v00, fmaf(v01, v01, qA));
            sB += v10 + v11; qB = fmaf(v10, v10, fmaf(v11, v11, qB));
        }
#pragma unroll
        for (int mk = 1; mk <= 2; mk <<= 1) {
            sA += __shfl_xor_sync(0xFFFFFFFF, sA, mk);
            qA += __shfl_xor_sync(0xFFFFFFFF, qA, mk);
            sB += __shfl_xor_sync(0xFFFFFFFF, sB, mk);
            qB += __shfl_xor_sync(0xFFFFFFFF, qB, mk);
        }
        if ((lane & 3) == 0) {
            atomicAdd(&g_sum[m0], sA);
            atomicAdd(&g_sqs[m0], qA);
            atomicAdd(&g_sum[m0 + 8], sB);
            atomicAdd(&g_sqs[m0 + 8], qB);
        }
    }
}

// ============================================================================
// Kernel D: finalize BN stats from accumulated sums
// ============================================================================
__global__ void bnfinal_kernel() {
    int o = threadIdx.x;
    const float invN = 1.f / (float)(B_ * HW);
    float m   = g_sum[o] * invN;
    float var = g_sqs[o] * invN - m * m;
    g_mean[o] = m;
    g_rstd[o] = rsqrtf(var + 1e-5f);
}

// ============================================================================
// Kernel E: normalize + affine + SiLU (in place, float4, fast exp)
// ============================================================================
__global__ void bnsilu_kernel(float* __restrict__ Y,
                              const float* __restrict__ gamma,
                              const float* __restrict__ beta) {
    size_t i4 = (size_t)blockIdx.x * blockDim.x + threadIdx.x;
    int o = (int)((i4 >> 10) & (COUT - 1));
    float m = g_mean[o], r = g_rstd[o], g = gamma[o], be = beta[o];
    float4 v = ((float4*)Y)[i4];
    float t;
    t = (v.x - m) * r * g + be; v.x = t / (1.f + __expf(-t));
    t = (v.y - m) * r * g + be; v.y = t / (1.f + __expf(-t));
    t = (v.z - m) * r * g + be; v.z = t / (1.f + __expf(-t));
    t = (v.w - m) * r * g + be; v.w = t / (1.f + __expf(-t));
    ((float4*)Y)[i4] = v;
}

// ============================================================================
// Launch
// ============================================================================
extern "C" void kernel_launch(void* const* d_in, const int* in_sizes, int n_in,
                              void* d_out, int out_size) {
    const float* x        = (const float*)d_in[0];
    const float* offset_w = (const float*)d_in[1];
    const float* offset_b = (const float*)d_in[2];
    const float* dconv_w  = (const float*)d_in[3];
    const float* dconv_b  = (const float*)d_in[4];
    const float* bn_gamma = (const float*)d_in[5];
    const float* bn_beta  = (const float*)d_in[6];
    float* out = (float*)d_out;

    __half *Ph, *Whi, *Wlo;
    cudaGetSymbolAddress((void**)&Ph,  g_Ph);
    cudaGetSymbolAddress((void**)&Whi, g_Whi);
    cudaGetSymbolAddress((void**)&Wlo, g_Wlo);

    static bool attr_set = false;
    if (!attr_set) {
        cudaFuncSetAttribute(gemm_mma_kernel,
                             cudaFuncAttributeMaxDynamicSharedMemorySize,
                             SMEM_GEMM);
        attr_set = true;
    }

    // A: offset conv partials
    offset_conv_part_kernel<<<dim3(256, NCHK), 128>>>(x, offset_w);

    // B2: split weights (fp16 hi/lo) + zero BN accumulators
    wsplit_kernel<<<(COUT * KD) / 256, 256>>>(dconv_w, Whi, Wlo);

    // B: gather (2 pixels/thread, single fp16 P)
    gather_kernel<<<(B_ * KK9 * HW / 2) / 256, 256>>>(x, offset_b, Ph);

    // C: fp16 2-pass HMMA GEMM + fused BN partial sums
    dim3 g(HW / 128, COUT / 128, B_);
    gemm_mma_kernel<<<g, 256, SMEM_GEMM>>>(Whi, Wlo, Ph, dconv_b, out);

    // D: finalize BN stats
    bnfinal_kernel<<<1, COUT>>>();

    // E: normalize + SiLU
    bnsilu_kernel<<<(B_ * COUT * HW / 4) / 256, 256>>>(out, bn_gamma, bn_beta);
}

// round 14
// speedup vs baseline: 1.6697x; 1.2374x over previous
#include <cuda_runtime.h>
#include <cuda_fp16.h>
#include <math.h>
#include <cstdint>

// Problem constants
#define B_    8
#define CIN   128
#define H_    64
#define W_    64
#define HW    (H_ * W_)        // 4096
#define COUT  256
#define KK9   9
#define OC18  18
#define KD    (CIN * KK9)      // 1152
#define NCHK  4                // offset-conv channel chunks
#define CCH   (CIN / NCHK)     // 32

// ---------------- scratch (device globals; no allocation allowed) -----------
__device__ float g_offp[NCHK * B_ * OC18 * HW];               // offset partials
__device__ __half g_Ph[(size_t)B_ * KD * HW];                 // P fp16 [b][k][n]
__device__ __half g_Wh[COUT * KD];                            // W fp16 [m][k]
__device__ float g_sum[COUT];
__device__ float g_sqs[COUT];
__device__ float g_mean[COUT];
__device__ float g_rstd[COUT];

// ============================================================================
// PTX helpers (plain sm_80+ instructions — compile for compute_103)
// ============================================================================
__device__ __forceinline__ uint32_t smem_u32(const void* p) {
    uint32_t a;
    asm("{ .reg .u64 t; cvta.to.shared.u64 t, %1; cvt.u32.u64 %0, t; }"
        : "=r"(a) : "l"(p));
    return a;
}
__device__ __forceinline__ void cpa16(uint32_t s, const void* g) {
    asm volatile("cp.async.cg.shared.global [%0], [%1], 16;" :: "r"(s), "l"(g));
}
#define CPA_COMMIT() asm volatile("cp.async.commit_group;" ::: "memory")
#define CPA_WAIT(N)  asm volatile("cp.async.wait_group %0;" :: "n"(N) : "memory")

__device__ __forceinline__ void ldsm4(uint32_t* r, uint32_t a) {
    asm volatile("ldmatrix.sync.aligned.m8n8.x4.shared.b16 {%0,%1,%2,%3}, [%4];"
                 : "=r"(r[0]), "=r"(r[1]), "=r"(r[2]), "=r"(r[3]) : "r"(a));
}
__device__ __forceinline__ void ldsm4t(uint32_t& r0, uint32_t& r1,
                                       uint32_t& r2, uint32_t& r3, uint32_t a) {
    asm volatile("ldmatrix.sync.aligned.m8n8.x4.trans.shared.b16 {%0,%1,%2,%3}, [%4];"
                 : "=r"(r0), "=r"(r1), "=r"(r2), "=r"(r3) : "r"(a));
}
// fp16 HMMA, fp32 accumulate
__device__ __forceinline__ void mma16816(float* d, const uint32_t* a,
                                         const uint32_t* b) {
    asm volatile(
        "mma.sync.aligned.m16n8k16.row.col.f32.f16.f16.f32 "
        "{%0,%1,%2,%3}, {%4,%5,%6,%7}, {%8,%9}, {%0,%1,%2,%3};"
        : "+f"(d[0]), "+f"(d[1]), "+f"(d[2]), "+f"(d[3])
        : "r"(a[0]), "r"(a[1]), "r"(a[2]), "r"(a[3]), "r"(b[0]), "r"(b[1]));
}

// ============================================================================
// Kernel A: offset conv partials (4 channel chunks) — unchanged
// ============================================================================
__global__ void offset_conv_part_kernel(const float* __restrict__ x,
                                        const float* __restrict__ w) {
    __shared__ float ws[OC18 * CCH * 9];
    int cc = blockIdx.y;
    for (int i = threadIdx.x; i < OC18 * CCH * 9; i += blockDim.x) {
        int oc = i / (CCH * 9);
        int r  = i - oc * (CCH * 9);
        ws[i] = w[oc * KD + cc * (CCH * 9) + r];
    }
    __syncthreads();

    int gid = blockIdx.x * blockDim.x + threadIdx.x;
    int b   = gid >> 12;
    int pix = gid & 4095;
    int y   = pix >> 6;
    int xx  = pix & 63;

    float acc[OC18];
#pragma unroll
    for (int oc = 0; oc < OC18; oc++) acc[oc] = 0.f;

    const float* xb = x + (size_t)b * CIN * HW + (size_t)cc * CCH * HW;
    for (int c = 0; c < CCH; c++) {
        const float* xc = xb + (size_t)c * HW;
        float v[9];
#pragma unroll
        for (int ky = 0; ky < 3; ky++) {
            int yy = y - 1 + ky;
            bool yv = (unsigned)yy < (unsigned)H_;
#pragma unroll
            for (int kx = 0; kx < 3; kx++) {
                int x2 = xx - 1 + kx;
                bool xv = (unsigned)x2 < (unsigned)W_;
                v[ky * 3 + kx] = (yv && xv) ? xc[yy * W_ + x2] : 0.f;
            }
        }
#pragma unroll
        for (int kk = 0; kk < 9; kk++) {
            float xvv = v[kk];
#pragma unroll
            for (int oc = 0; oc < OC18; oc++)
                acc[oc] = fmaf(xvv, ws[oc * (CCH * 9) + c * 9 + kk], acc[oc]);
        }
    }

    float* ob = g_offp + (((size_t)cc * B_ + b) * OC18) * HW + pix;
#pragma unroll
    for (int oc = 0; oc < OC18; oc++) ob[(size_t)oc * HW] = acc[oc];
}

// ============================================================================
// Kernel B: deformable bilinear gather, 2 pixels/thread -> single fp16 P
// ============================================================================
__global__ void gather_kernel(const float* __restrict__ x,
                              const float* __restrict__ offset_b,
                              __half* __restrict__ Ph) {
    int gid = blockIdx.x * blockDim.x + threadIdx.x;    // < 147456
    int p2  = gid & 2047;           // pixel pair
    int t   = gid >> 11;            // b*9 + kk
    int kk  = t % 9;
    int b   = t / 9;
    int n0  = p2 * 2;

    float bdy = offset_b[2 * kk + 0];
    float bdx = offset_b[2 * kk + 1];

    int   i00[2], i01[2], i10[2], i11[2];
    float w00[2], w01[2], w10[2], w11[2];

#pragma unroll
    for (int u = 0; u < 2; u++) {
        int n  = n0 + u;
        int y  = n >> 6;
        int xx = n & 63;
        float dy = bdy, dx = bdx;
#pragma unroll
        for (int p = 0; p < NCHK; p++) {
            const float* ob = g_offp + (((size_t)p * B_ + b) * OC18) * HW + n;
            dy += ob[(size_t)(2 * kk + 0) * HW];
            dx += ob[(size_t)(2 * kk + 1) * HW];
        }
        float sy = (float)(y - 1 + kk / 3) + dy;
        float sx = (float)(xx - 1 + kk % 3) + dx;
        float fy = floorf(sy), fx = floorf(sx);
        int y0 = (int)fy, x0 = (int)fx;
        int y1 = y0 + 1, x1 = x0 + 1;
        float wy = sy - fy, wx = sx - fx;
        bool vy0 = (unsigned)y0 < (unsigned)H_;
        bool vy1 = (unsigned)y1 < (unsigned)H_;
        bool vx0 = (unsigned)x0 < (unsigned)W_;
        bool vx1 = (unsigned)x1 < (unsigned)W_;
        int cy0 = min(max(y0, 0), H_ - 1), cy1 = min(max(y1, 0), H_ - 1);
        int cx0 = min(max(x0, 0), W_ - 1), cx1 = min(max(x1, 0), W_ - 1);
        i00[u] = cy0 * W_ + cx0;
        i01[u] = cy0 * W_ + cx1;
        i10[u] = cy1 * W_ + cx0;
        i11[u] = cy1 * W_ + cx1;
        w00[u] = (1.f - wy) * (1.f - wx) * (float)(vy0 && vx0);
        w01[u] = (1.f - wy) * wx         * (float)(vy0 && vx1);
        w10[u] = wy * (1.f - wx)         * (float)(vy1 && vx0);
        w11[u] = wy * wx                 * (float)(vy1 && vx1);
    }

    const float* xb = x + (size_t)b * CIN * HW;
    size_t base = ((size_t)b * KD + kk) * HW + n0;

#pragma unroll 2
    for (int c = 0; c < CIN; c++) {
        const float* xc = xb + (size_t)c * HW;
        size_t idx = base + (size_t)c * (KK9 * HW);
        float v0 = w00[0] * xc[i00[0]] + w01[0] * xc[i01[0]]
                 + w10[0] * xc[i10[0]] + w11[0] * xc[i11[0]];
        float v1 = w00[1] * xc[i00[1]] + w01[1] * xc[i01[1]]
                 + w10[1] * xc[i10[1]] + w11[1] * xc[i11[1]];
        *(__half2*)(Ph + idx) = __floats2half2_rn(v0, v1);
    }
}

// ============================================================================
// Kernel B2: convert dconv weights to fp16; also zero BN accumulators
// ============================================================================
__global__ void wsplit_kernel(const float* __restrict__ w,
                              __half* __restrict__ hi) {
    int i = blockIdx.x * blockDim.x + threadIdx.x;
    if (i < COUT) { g_sum[i] = 0.f; g_sqs[i] = 0.f; }
    hi[i] = __float2half_rn(w[i]);
}

// ============================================================================
// Kernel C: HMMA GEMM  Y[b] = W[256,1152] @ P[b][1152,4096] + bias
// Pure fp16 single pass, fp32 accum. 8 warps, 64x32 warp tile, BK=32,
// 2-stage cp.async (loads before wait), launch_bounds(256,2).
// Fused BN partial sums via shuffle + atomics in the epilogue.
// ============================================================================
#define BK      32
#define NC      (KD / BK)        // 36
#define A_STR   40
#define B_STR   136
#define AH_OFF  0
#define BH_OFF  (128 * A_STR)                // 5120
#define STG     (BH_OFF + 32 * B_STR)        // 9472 halves / stage
#define SMEM_GEMM (2 * STG * 2)              // 37888 bytes

__global__ void __launch_bounds__(256, 2)
gemm_mma_kernel(const __half* __restrict__ Wh,
                const __half* __restrict__ Ph,
                const float* __restrict__ bias,
                float* __restrict__ Y) {
    extern __shared__ __half sm[];
    const uint32_t sbase = smem_u32(sm);

    int tid  = threadIdx.x;
    int wid  = tid >> 5;
    int lane = tid & 31;
    int bn = blockIdx.x * 128;
    int bm = blockIdx.y * 128;
    int b  = blockIdx.z;

    int wm = (wid >> 2) * 64;    // warp m offset
    int wn = (wid & 3) * 32;     // warp n offset

    const __half* Pb = Ph + (size_t)b * KD * HW;

    float acc[4][4][4];
#pragma unroll
    for (int i = 0; i < 4; i++)
#pragma unroll
        for (int j = 0; j < 4; j++)
#pragma unroll
            for (int q = 0; q < 4; q++) acc[i][j][q] = 0.f;

    auto load_stage = [&](int chunk, int st) {
        int k0 = chunk * BK;
        uint32_t s0 = sbase + (uint32_t)(st * STG) * 2;
#pragma unroll
        for (int i = 0; i < 2; i++) {
            int idx = tid + i * 256;
            int m   = idx >> 2;
            int kq  = (idx & 3) << 3;
            size_t go = (size_t)(bm + m) * KD + k0 + kq;
            uint32_t sa = s0 + (uint32_t)(m * A_STR + kq) * 2;
            cpa16(sa + AH_OFF * 2, Wh + go);
        }
#pragma unroll
        for (int i = 0; i < 2; i++) {
            int idx = tid + i * 256;
            int k   = idx >> 4;
            int nq  = (idx & 15) << 3;
            size_t go = (size_t)(k0 + k) * HW + bn + nq;
            uint32_t sa = s0 + (uint32_t)(k * B_STR + nq) * 2;
            cpa16(sa + BH_OFF * 2, Pb + go);
        }
        CPA_COMMIT();
    };

    load_stage(0, 0);

    int row  = lane & 15;
    int half = (lane >> 4) << 3;

    for (int c = 0; c < NC; c++) {
        int st = c & 1;
        if (c + 1 < NC) {
            load_stage(c + 1, st ^ 1);   // issue next-stage loads FIRST
            CPA_WAIT(1);
        } else {
            CPA_WAIT(0);
        }
        __syncthreads();

        uint32_t s0 = sbase + (uint32_t)(st * STG) * 2;

#pragma unroll
        for (int ks = 0; ks < BK; ks += 16) {
            uint32_t ah[4][4], bh[4][2];
#pragma unroll
            for (int i = 0; i < 4; i++) {
                uint32_t a = s0 + (uint32_t)((wm + i * 16 + row) * A_STR + ks + half) * 2;
                ldsm4(ah[i], a + AH_OFF * 2);
            }
#pragma unroll
            for (int j = 0; j < 2; j++) {
                uint32_t a = s0 + (uint32_t)((ks + row) * B_STR + wn + j * 16 + half) * 2;
                uint32_t r0, r1, r2, r3;
                ldsm4t(r0, r1, r2, r3, a + BH_OFF * 2);
                bh[2 * j][0] = r0; bh[2 * j][1] = r1;
                bh[2 * j + 1][0] = r2; bh[2 * j + 1][1] = r3;
            }
#pragma unroll
            for (int i = 0; i < 4; i++)
#pragma unroll
                for (int j = 0; j < 4; j++)
                    mma16816(acc[i][j], ah[i], bh[j]);
        }
        __syncthreads();
    }

    // --- epilogue: add bias, write Y, fused BN partial sums ---
    int r  = lane >> 2;
    int c2 = (lane & 3) << 1;
#pragma unroll
    for (int i = 0; i < 4; i++) {
        int m0 = bm + wm + i * 16 + r;
        float b0 = bias[m0];
        float b1 = bias[m0 + 8];
        float* y0 = Y + ((size_t)b * COUT + m0) * HW + bn + wn + c2;
        float* y1 = y0 + (size_t)8 * HW;
        float sA = 0.f, qA = 0.f, sB = 0.f, qB = 0.f;
#pragma unroll
        for (int j = 0; j < 4; j++) {
            float v00 = acc[i][j][0] + b0, v01 = acc[i][j][1] + b0;
            float v10 = acc[i][j][2] + b1, v11 = acc[i][j][3] + b1;
            *(float2*)(y0 + j * 8) = make_float2(v00, v01);
            *(float2*)(y1 + j * 8) = make_float2(v10, v11);
            sA += v00 + v01; qA = fmaf(v00, v00, fmaf(v01, v01, qA));
            sB += v10 + v11; qB = fmaf(v10, v10, fmaf(v11, v11, qB));
        }
#pragma unroll
        for (int mk = 1; mk <= 2; mk <<= 1) {
            sA += __shfl_xor_sync(0xFFFFFFFF, sA, mk);
            qA += __shfl_xor_sync(0xFFFFFFFF, qA, mk);
            sB += __shfl_xor_sync(0xFFFFFFFF, sB, mk);
            qB += __shfl_xor_sync(0xFFFFFFFF, qB, mk);
        }
        if ((lane & 3) == 0) {
            atomicAdd(&g_sum[m0], sA);
            atomicAdd(&g_sqs[m0], qA);
            atomicAdd(&g_sum[m0 + 8], sB);
            atomicAdd(&g_sqs[m0 + 8], qB);
        }
    }
}

// ============================================================================
// Kernel D: finalize BN stats from accumulated sums
// ============================================================================
__global__ void bnfinal_kernel() {
    int o = threadIdx.x;
    const float invN = 1.f / (float)(B_ * HW);
    float m   = g_sum[o] * invN;
    float var = g_sqs[o] * invN - m * m;
    g_mean[o] = m;
    g_rstd[o] = rsqrtf(var + 1e-5f);
}

// ============================================================================
// Kernel E: normalize + affine + SiLU (in place, float4, fast exp)
// ============================================================================
__global__ void bnsilu_kernel(float* __restrict__ Y,
                              const float* __restrict__ gamma,
                              const float* __restrict__ beta) {
    size_t i4 = (size_t)blockIdx.x * blockDim.x + threadIdx.x;
    int o = (int)((i4 >> 10) & (COUT - 1));
    float m = g_mean[o], r = g_rstd[o], g = gamma[o], be = beta[o];
    float4 v = ((float4*)Y)[i4];
    float t;
    t = (v.x - m) * r * g + be; v.x = t / (1.f + __expf(-t));
    t = (v.y - m) * r * g + be; v.y = t / (1.f + __expf(-t));
    t = (v.z - m) * r * g + be; v.z = t / (1.f + __expf(-t));
    t = (v.w - m) * r * g + be; v.w = t / (1.f + __expf(-t));
    ((float4*)Y)[i4] = v;
}

// ============================================================================
// Launch
// ============================================================================
extern "C" void kernel_launch(void* const* d_in, const int* in_sizes, int n_in,
                              void* d_out, int out_size) {
    const float* x        = (const float*)d_in[0];
    const float* offset_w = (const float*)d_in[1];
    const float* offset_b = (const float*)d_in[2];
    const float* dconv_w  = (const float*)d_in[3];
    const float* dconv_b  = (const float*)d_in[4];
    const float* bn_gamma = (const float*)d_in[5];
    const float* bn_beta  = (const float*)d_in[6];
    float* out = (float*)d_out;

    __half *Ph, *Wh;
    cudaGetSymbolAddress((void**)&Ph, g_Ph);
    cudaGetSymbolAddress((void**)&Wh, g_Wh);

    static bool attr_set = false;
    if (!attr_set) {
        cudaFuncSetAttribute(gemm_mma_kernel,
                             cudaFuncAttributeMaxDynamicSharedMemorySize,
                             SMEM_GEMM);
        attr_set = true;
    }

    // A: offset conv partials
    offset_conv_part_kernel<<<dim3(256, NCHK), 128>>>(x, offset_w);

    // B2: convert weights to fp16 + zero BN accumulators
    wsplit_kernel<<<(COUT * KD) / 256, 256>>>(dconv_w, Wh);

    // B: gather (2 pixels/thread, single fp16 P)
    gather_kernel<<<(B_ * KK9 * HW / 2) / 256, 256>>>(x, offset_b, Ph);

    // C: pure fp16 single-pass HMMA GEMM + fused BN partial sums
    dim3 g(HW / 128, COUT / 128, B_);
    gemm_mma_kernel<<<g, 256, SMEM_GEMM>>>(Wh, Ph, dconv_b, out);

    // D: finalize BN stats
    bnfinal_kernel<<<1, COUT>>>();

    // E: normalize + SiLU
    bnsilu_kernel<<<(B_ * COUT * HW / 4) / 256, 256>>>(out, bn_gamma, bn_beta);
}

// round 16
// speedup vs baseline: 1.6999x; 1.0181x over previous
#include <cuda_runtime.h>
#include <cuda_fp16.h>
#include <math.h>
#include <cstdint>

// Problem constants
#define B_    8
#define CIN   128
#define H_    64
#define W_    64
#define HW    (H_ * W_)        // 4096
#define COUT  256
#define KK9   9
#define OC18  18
#define KD    (CIN * KK9)      // 1152
#define NCHK  4                // offset-conv channel chunks
#define CCH   (CIN / NCHK)     // 32

// ---------------- scratch (device globals; no allocation allowed) -----------
__device__ float g_offp[NCHK * B_ * OC18 * HW];               // offset partials
__device__ __half g_xh[(size_t)B_ * CIN * HW];                // x as fp16
__device__ __half g_Ph[(size_t)B_ * KD * HW];                 // P fp16 [b][k][n]
__device__ __half g_Wh[COUT * KD];                            // W fp16 [m][k]
__device__ float g_sum[COUT];
__device__ float g_sqs[COUT];
__device__ float g_mean[COUT];
__device__ float g_rstd[COUT];

// ============================================================================
// PTX helpers (plain sm_80+ instructions — compile for compute_103)
// ============================================================================
__device__ __forceinline__ uint32_t smem_u32(const void* p) {
    uint32_t a;
    asm("{ .reg .u64 t; cvta.to.shared.u64 t, %1; cvt.u32.u64 %0, t; }"
        : "=r"(a) : "l"(p));
    return a;
}
__device__ __forceinline__ void cpa16(uint32_t s, const void* g) {
    asm volatile("cp.async.cg.shared.global [%0], [%1], 16;" :: "r"(s), "l"(g));
}
#define CPA_COMMIT() asm volatile("cp.async.commit_group;" ::: "memory")
#define CPA_WAIT(N)  asm volatile("cp.async.wait_group %0;" :: "n"(N) : "memory")

__device__ __forceinline__ void ldsm4(uint32_t* r, uint32_t a) {
    asm volatile("ldmatrix.sync.aligned.m8n8.x4.shared.b16 {%0,%1,%2,%3}, [%4];"
                 : "=r"(r[0]), "=r"(r[1]), "=r"(r[2]), "=r"(r[3]) : "r"(a));
}
__device__ __forceinline__ void ldsm4t(uint32_t& r0, uint32_t& r1,
                                       uint32_t& r2, uint32_t& r3, uint32_t a) {
    asm volatile("ldmatrix.sync.aligned.m8n8.x4.trans.shared.b16 {%0,%1,%2,%3}, [%4];"
                 : "=r"(r0), "=r"(r1), "=r"(r2), "=r"(r3) : "r"(a));
}
// fp16 HMMA, fp32 accumulate
__device__ __forceinline__ void mma16816(float* d, const uint32_t* a,
                                         const uint32_t* b) {
    asm volatile(
        "mma.sync.aligned.m16n8k16.row.col.f32.f16.f16.f32 "
        "{%0,%1,%2,%3}, {%4,%5,%6,%7}, {%8,%9}, {%0,%1,%2,%3};"
        : "+f"(d[0]), "+f"(d[1]), "+f"(d[2]), "+f"(d[3])
        : "r"(a[0]), "r"(a[1]), "r"(a[2]), "r"(a[3]), "r"(b[0]), "r"(b[1]));
}

// ============================================================================
// Kernel X2H: convert x to fp16 (float4 -> 4x half)
// ============================================================================
__global__ void x2h_kernel(const float* __restrict__ x, __half* __restrict__ xh) {
    size_t i4 = (size_t)blockIdx.x * blockDim.x + threadIdx.x;  // < 1048576
    float4 v = ((const float4*)x)[i4];
    __half2 h0 = __floats2half2_rn(v.x, v.y);
    __half2 h1 = __floats2half2_rn(v.z, v.w);
    uint2 o;
    o.x = *(uint32_t*)&h0;
    o.y = *(uint32_t*)&h1;
    ((uint2*)xh)[i4] = o;
}

// ============================================================================
// Kernel A: offset conv partials (4 channel chunks) — unchanged (fp32 x)
// ============================================================================
__global__ void offset_conv_part_kernel(const float* __restrict__ x,
                                        const float* __restrict__ w) {
    __shared__ float ws[OC18 * CCH * 9];
    int cc = blockIdx.y;
    for (int i = threadIdx.x; i < OC18 * CCH * 9; i += blockDim.x) {
        int oc = i / (CCH * 9);
        int r  = i - oc * (CCH * 9);
        ws[i] = w[oc * KD + cc * (CCH * 9) + r];
    }
    __syncthreads();

    int gid = blockIdx.x * blockDim.x + threadIdx.x;
    int b   = gid >> 12;
    int pix = gid & 4095;
    int y   = pix >> 6;
    int xx  = pix & 63;

    float acc[OC18];
#pragma unroll
    for (int oc = 0; oc < OC18; oc++) acc[oc] = 0.f;

    const float* xb = x + (size_t)b * CIN * HW + (size_t)cc * CCH * HW;
    for (int c = 0; c < CCH; c++) {
        const float* xc = xb + (size_t)c * HW;
        float v[9];
#pragma unroll
        for (int ky = 0; ky < 3; ky++) {
            int yy = y - 1 + ky;
            bool yv = (unsigned)yy < (unsigned)H_;
#pragma unroll
            for (int kx = 0; kx < 3; kx++) {
                int x2 = xx - 1 + kx;
                bool xv = (unsigned)x2 < (unsigned)W_;
                v[ky * 3 + kx] = (yv && xv) ? xc[yy * W_ + x2] : 0.f;
            }
        }
#pragma unroll
        for (int kk = 0; kk < 9; kk++) {
            float xvv = v[kk];
#pragma unroll
            for (int oc = 0; oc < OC18; oc++)
                acc[oc] = fmaf(xvv, ws[oc * (CCH * 9) + c * 9 + kk], acc[oc]);
        }
    }

    float* ob = g_offp + (((size_t)cc * B_ + b) * OC18) * HW + pix;
#pragma unroll
    for (int oc = 0; oc < OC18; oc++) ob[(size_t)oc * HW] = acc[oc];
}

// ============================================================================
// Kernel B: deformable bilinear gather, 2 pixels/thread, fp16 x corners
// ============================================================================
__global__ void gather_kernel(const __half* __restrict__ xh,
                              const float* __restrict__ offset_b,
                              __half* __restrict__ Ph) {
    int gid = blockIdx.x * blockDim.x + threadIdx.x;    // < 147456
    int p2  = gid & 2047;           // pixel pair
    int t   = gid >> 11;            // b*9 + kk
    int kk  = t % 9;
    int b   = t / 9;
    int n0  = p2 * 2;

    float bdy = offset_b[2 * kk + 0];
    float bdx = offset_b[2 * kk + 1];

    int   i00[2], i01[2], i10[2], i11[2];
    float w00[2], w01[2], w10[2], w11[2];

#pragma unroll
    for (int u = 0; u < 2; u++) {
        int n  = n0 + u;
        int y  = n >> 6;
        int xx = n & 63;
        float dy = bdy, dx = bdx;
#pragma unroll
        for (int p = 0; p < NCHK; p++) {
            const float* ob = g_offp + (((size_t)p * B_ + b) * OC18) * HW + n;
            dy += ob[(size_t)(2 * kk + 0) * HW];
            dx += ob[(size_t)(2 * kk + 1) * HW];
        }
        float sy = (float)(y - 1 + kk / 3) + dy;
        float sx = (float)(xx - 1 + kk % 3) + dx;
        float fy = floorf(sy), fx = floorf(sx);
        int y0 = (int)fy, x0 = (int)fx;
        int y1 = y0 + 1, x1 = x0 + 1;
        float wy = sy - fy, wx = sx - fx;
        bool vy0 = (unsigned)y0 < (unsigned)H_;
        bool vy1 = (unsigned)y1 < (unsigned)H_;
        bool vx0 = (unsigned)x0 < (unsigned)W_;
        bool vx1 = (unsigned)x1 < (unsigned)W_;
        int cy0 = min(max(y0, 0), H_ - 1), cy1 = min(max(y1, 0), H_ - 1);
        int cx0 = min(max(x0, 0), W_ - 1), cx1 = min(max(x1, 0), W_ - 1);
        i00[u] = cy0 * W_ + cx0;
        i01[u] = cy0 * W_ + cx1;
        i10[u] = cy1 * W_ + cx0;
        i11[u] = cy1 * W_ + cx1;
        w00[u] = (1.f - wy) * (1.f - wx) * (float)(vy0 && vx0);
        w01[u] = (1.f - wy) * wx         * (float)(vy0 && vx1);
        w10[u] = wy * (1.f - wx)         * (float)(vy1 && vx0);
        w11[u] = wy * wx                 * (float)(vy1 && vx1);
    }

    const __half* xb = xh + (size_t)b * CIN * HW;
    size_t base = ((size_t)b * KD + kk) * HW + n0;

#pragma unroll 2
    for (int c = 0; c < CIN; c++) {
        const __half* xc = xb + (size_t)c * HW;
        size_t idx = base + (size_t)c * (KK9 * HW);
        float v0 = w00[0] * __half2float(xc[i00[0]])
                 + w01[0] * __half2float(xc[i01[0]])
                 + w10[0] * __half2float(xc[i10[0]])
                 + w11[0] * __half2float(xc[i11[0]]);
        float v1 = w00[1] * __half2float(xc[i00[1]])
                 + w01[1] * __half2float(xc[i01[1]])
                 + w10[1] * __half2float(xc[i10[1]])
                 + w11[1] * __half2float(xc[i11[1]]);
        *(__half2*)(Ph + idx) = __floats2half2_rn(v0, v1);
    }
}

// ============================================================================
// Kernel B2: convert dconv weights to fp16; also zero BN accumulators
// ============================================================================
__global__ void wsplit_kernel(const float* __restrict__ w,
                              __half* __restrict__ hi) {
    int i = blockIdx.x * blockDim.x + threadIdx.x;
    if (i < COUT) { g_sum[i] = 0.f; g_sqs[i] = 0.f; }
    hi[i] = __float2half_rn(w[i]);
}

// ============================================================================
// Kernel C: HMMA GEMM  Y[b] = W[256,1152] @ P[b][1152,4096] + bias
// Pure fp16 single pass, fp32 accum. R14 winner, frozen.
// ============================================================================
#define BK      32
#define NC      (KD / BK)        // 36
#define A_STR   40
#define B_STR   136
#define AH_OFF  0
#define BH_OFF  (128 * A_STR)                // 5120
#define STG     (BH_OFF + 32 * B_STR)        // 9472 halves / stage
#define SMEM_GEMM (2 * STG * 2)              // 37888 bytes

__global__ void __launch_bounds__(256, 2)
gemm_mma_kernel(const __half* __restrict__ Wh,
                const __half* __restrict__ Ph,
                const float* __restrict__ bias,
                float* __restrict__ Y) {
    extern __shared__ __half sm[];
    const uint32_t sbase = smem_u32(sm);

    int tid  = threadIdx.x;
    int wid  = tid >> 5;
    int lane = tid & 31;
    int bn = blockIdx.x * 128;
    int bm = blockIdx.y * 128;
    int b  = blockIdx.z;

    int wm = (wid >> 2) * 64;    // warp m offset
    int wn = (wid & 3) * 32;     // warp n offset

    const __half* Pb = Ph + (size_t)b * KD * HW;

    float acc[4][4][4];
#pragma unroll
    for (int i = 0; i < 4; i++)
#pragma unroll
        for (int j = 0; j < 4; j++)
#pragma unroll
            for (int q = 0; q < 4; q++) acc[i][j][q] = 0.f;

    auto load_stage = [&](int chunk, int st) {
        int k0 = chunk * BK;
        uint32_t s0 = sbase + (uint32_t)(st * STG) * 2;
#pragma unroll
        for (int i = 0; i < 2; i++) {
            int idx = tid + i * 256;
            int m   = idx >> 2;
            int kq  = (idx & 3) << 3;
            size_t go = (size_t)(bm + m) * KD + k0 + kq;
            uint32_t sa = s0 + (uint32_t)(m * A_STR + kq) * 2;
            cpa16(sa + AH_OFF * 2, Wh + go);
        }
#pragma unroll
        for (int i = 0; i < 2; i++) {
            int idx = tid + i * 256;
            int k   = idx >> 4;
            int nq  = (idx & 15) << 3;
            size_t go = (size_t)(k0 + k) * HW + bn + nq;
            uint32_t sa = s0 + (uint32_t)(k * B_STR + nq) * 2;
            cpa16(sa + BH_OFF * 2, Pb + go);
        }
        CPA_COMMIT();
    };

    load_stage(0, 0);

    int row  = lane & 15;
    int half = (lane >> 4) << 3;

    for (int c = 0; c < NC; c++) {
        int st = c & 1;
        if (c + 1 < NC) {
            load_stage(c + 1, st ^ 1);   // issue next-stage loads FIRST
            CPA_WAIT(1);
        } else {
            CPA_WAIT(0);
        }
        __syncthreads();

        uint32_t s0 = sbase + (uint32_t)(st * STG) * 2;

#pragma unroll
        for (int ks = 0; ks < BK; ks += 16) {
            uint32_t ah[4][4], bh[4][2];
#pragma unroll
            for (int i = 0; i < 4; i++) {
                uint32_t a = s0 + (uint32_t)((wm + i * 16 + row) * A_STR + ks + half) * 2;
                ldsm4(ah[i], a + AH_OFF * 2);
            }
#pragma unroll
            for (int j = 0; j < 2; j++) {
                uint32_t a = s0 + (uint32_t)((ks + row) * B_STR + wn + j * 16 + half) * 2;
                uint32_t r0, r1, r2, r3;
                ldsm4t(r0, r1, r2, r3, a + BH_OFF * 2);
                bh[2 * j][0] = r0; bh[2 * j][1] = r1;
                bh[2 * j + 1][0] = r2; bh[2 * j + 1][1] = r3;
            }
#pragma unroll
            for (int i = 0; i < 4; i++)
#pragma unroll
                for (int j = 0; j < 4; j++)
                    mma16816(acc[i][j], ah[i], bh[j]);
        }
        __syncthreads();
    }

    // --- epilogue: add bias, write Y, fused BN partial sums ---
    int r  = lane >> 2;
    int c2 = (lane & 3) << 1;
#pragma unroll
    for (int i = 0; i < 4; i++) {
        int m0 = bm + wm + i * 16 + r;
        float b0 = bias[m0];
        float b1 = bias[m0 + 8];
        float* y0 = Y + ((size_t)b * COUT + m0) * HW + bn + wn + c2;
        float* y1 = y0 + (size_t)8 * HW;
        float sA = 0.f, qA = 0.f, sB = 0.f, qB = 0.f;
#pragma unroll
        for (int j = 0; j < 4; j++) {
            float v00 = acc[i][j][0] + b0, v01 = acc[i][j][1] + b0;
            float v10 = acc[i][j][2] + b1, v11 = acc[i][j][3] + b1;
            *(float2*)(y0 + j * 8) = make_float2(v00, v01);
            *(float2*)(y1 + j * 8) = make_float2(v10, v11);
            sA += v00 + v01; qA = fmaf(v00, v00, fmaf(v01, v01, qA));
            sB += v10 + v11; qB = fmaf(v10, v10, fmaf(v11, v11, qB));
        }
#pragma unroll
        for (int mk = 1; mk <= 2; mk <<= 1) {
            sA += __shfl_xor_sync(0xFFFFFFFF, sA, mk);
            qA += __shfl_xor_sync(0xFFFFFFFF, qA, mk);
            sB += __shfl_xor_sync(0xFFFFFFFF, sB, mk);
            qB += __shfl_xor_sync(0xFFFFFFFF, qB, mk);
        }
        if ((lane & 3) == 0) {
            atomicAdd(&g_sum[m0], sA);
            atomicAdd(&g_sqs[m0], qA);
            atomicAdd(&g_sum[m0 + 8], sB);
            atomicAdd(&g_sqs[m0 + 8], qB);
        }
    }
}

// ============================================================================
// Kernel D: finalize BN stats from accumulated sums
// ============================================================================
__global__ void bnfinal_kernel() {
    int o = threadIdx.x;
    const float invN = 1.f / (float)(B_ * HW);
    float m   = g_sum[o] * invN;
    float var = g_sqs[o] * invN - m * m;
    g_mean[o] = m;
    g_rstd[o] = rsqrtf(var + 1e-5f);
}

// ============================================================================
// Kernel E: normalize + affine + SiLU (in place, float4, fast exp)
// ============================================================================
__global__ void bnsilu_kernel(float* __restrict__ Y,
                              const float* __restrict__ gamma,
                              const float* __restrict__ beta) {
    size_t i4 = (size_t)blockIdx.x * blockDim.x + threadIdx.x;
    int o = (int)((i4 >> 10) & (COUT - 1));
    float m = g_mean[o], r = g_rstd[o], g = gamma[o], be = beta[o];
    float4 v = ((float4*)Y)[i4];
    float t;
    t = (v.x - m) * r * g + be; v.x = t / (1.f + __expf(-t));
    t = (v.y - m) * r * g + be; v.y = t / (1.f + __expf(-t));
    t = (v.z - m) * r * g + be; v.z = t / (1.f + __expf(-t));
    t = (v.w - m) * r * g + be; v.w = t / (1.f + __expf(-t));
    ((float4*)Y)[i4] = v;
}

// ============================================================================
// Launch
// ============================================================================
extern "C" void kernel_launch(void* const* d_in, const int* in_sizes, int n_in,
                              void* d_out, int out_size) {
    const float* x        = (const float*)d_in[0];
    const float* offset_w = (const float*)d_in[1];
    const float* offset_b = (const float*)d_in[2];
    const float* dconv_w  = (const float*)d_in[3];
    const float* dconv_b  = (const float*)d_in[4];
    const float* bn_gamma = (const float*)d_in[5];
    const float* bn_beta  = (const float*)d_in[6];
    float* out = (float*)d_out;

    __half *Ph, *Wh, *Xh;
    cudaGetSymbolAddress((void**)&Ph, g_Ph);
    cudaGetSymbolAddress((void**)&Wh, g_Wh);
    cudaGetSymbolAddress((void**)&Xh, g_xh);

    static bool attr_set = false;
    if (!attr_set) {
        cudaFuncSetAttribute(gemm_mma_kernel,
                             cudaFuncAttributeMaxDynamicSharedMemorySize,
                             SMEM_GEMM);
        attr_set = true;
    }

    // X2H: convert x to fp16 (needed by gather; runs before offset conv for slack)
    x2h_kernel<<<(B_ * CIN * HW / 4) / 256, 256>>>(x, Xh);

    // A: offset conv partials
    offset_conv_part_kernel<<<dim3(256, NCHK), 128>>>(x, offset_w);

    // B2: convert weights to fp16 + zero BN accumulators
    wsplit_kernel<<<(COUT * KD) / 256, 256>>>(dconv_w, Wh);

    // B: gather (2 pixels/thread, fp16 x corners, fp16 P)
    gather_kernel<<<(B_ * KK9 * HW / 2) / 256, 256>>>(Xh, offset_b, Ph);

    // C: pure fp16 single-pass HMMA GEMM + fused BN partial sums
    dim3 g(HW / 128, COUT / 128, B_);
    gemm_mma_kernel<<<g, 256, SMEM_GEMM>>>(Wh, Ph, dconv_b, out);

    // D: finalize BN stats
    bnfinal_kernel<<<1, COUT>>>();

    // E: normalize + SiLU
    bnsilu_kernel<<<(B_ * COUT * HW / 4) / 256, 256>>>(out, bn_gamma, bn_beta);
}

// round 17
// speedup vs baseline: 1.7610x; 1.0360x over previous
#include <cuda_runtime.h>
#include <cuda_fp16.h>
#include <math.h>
#include <cstdint>

// Problem constants
#define B_    8
#define CIN   128
#define H_    64
#define W_    64
#define HW    (H_ * W_)        // 4096
#define COUT  256
#define KK9   9
#define OC18  18
#define KD    (CIN * KK9)      // 1152
#define NCHK  4                // offset-conv channel chunks
#define CCH   (CIN / NCHK)     // 32

// ---------------- scratch (device globals; no allocation allowed) -----------
__device__ float g_offp[NCHK * B_ * OC18 * HW];               // offset partials
__device__ __half g_xh[(size_t)B_ * CIN * HW];                // x as fp16
__device__ __half g_Ph[(size_t)B_ * KD * HW];                 // P fp16 [b][k][n]
__device__ __half g_Wh[COUT * KD];                            // W fp16 [m][k]
__device__ float g_sum[COUT];
__device__ float g_sqs[COUT];

// ============================================================================
// PTX helpers (plain sm_80+ instructions — compile for compute_103)
// ============================================================================
__device__ __forceinline__ uint32_t smem_u32(const void* p) {
    uint32_t a;
    asm("{ .reg .u64 t; cvta.to.shared.u64 t, %1; cvt.u32.u64 %0, t; }"
        : "=r"(a) : "l"(p));
    return a;
}
__device__ __forceinline__ void cpa16(uint32_t s, const void* g) {
    asm volatile("cp.async.cg.shared.global [%0], [%1], 16;" :: "r"(s), "l"(g));
}
#define CPA_COMMIT() asm volatile("cp.async.commit_group;" ::: "memory")
#define CPA_WAIT(N)  asm volatile("cp.async.wait_group %0;" :: "n"(N) : "memory")

__device__ __forceinline__ void ldsm4(uint32_t* r, uint32_t a) {
    asm volatile("ldmatrix.sync.aligned.m8n8.x4.shared.b16 {%0,%1,%2,%3}, [%4];"
                 : "=r"(r[0]), "=r"(r[1]), "=r"(r[2]), "=r"(r[3]) : "r"(a));
}
__device__ __forceinline__ void ldsm4t(uint32_t& r0, uint32_t& r1,
                                       uint32_t& r2, uint32_t& r3, uint32_t a) {
    asm volatile("ldmatrix.sync.aligned.m8n8.x4.trans.shared.b16 {%0,%1,%2,%3}, [%4];"
                 : "=r"(r0), "=r"(r1), "=r"(r2), "=r"(r3) : "r"(a));
}
// fp16 HMMA, fp32 accumulate
__device__ __forceinline__ void mma16816(float* d, const uint32_t* a,
                                         const uint32_t* b) {
    asm volatile(
        "mma.sync.aligned.m16n8k16.row.col.f32.f16.f16.f32 "
        "{%0,%1,%2,%3}, {%4,%5,%6,%7}, {%8,%9}, {%0,%1,%2,%3};"
        : "+f"(d[0]), "+f"(d[1]), "+f"(d[2]), "+f"(d[3])
        : "r"(a[0]), "r"(a[1]), "r"(a[2]), "r"(a[3]), "r"(b[0]), "r"(b[1]));
}

// ============================================================================
// Kernel P: prep — x->fp16, W->fp16, zero BN accumulators (fused)
// Grid: 4096 x 256 threads (1048576 = B*CIN*HW/4 float4s)
// ============================================================================
__global__ void prep_kernel(const float* __restrict__ x, __half* __restrict__ xh,
                            const float* __restrict__ w, __half* __restrict__ wh) {
    int i = blockIdx.x * blockDim.x + threadIdx.x;      // < 1048576
    float4 v = ((const float4*)x)[i];
    __half2 h0 = __floats2half2_rn(v.x, v.y);
    __half2 h1 = __floats2half2_rn(v.z, v.w);
    uint2 o;
    o.x = *(uint32_t*)&h0;
    o.y = *(uint32_t*)&h1;
    ((uint2*)xh)[i] = o;
    if (i < COUT * KD) wh[i] = __float2half_rn(w[i]);
    if (i < COUT) { g_sum[i] = 0.f; g_sqs[i] = 0.f; }
}

// ============================================================================
// Kernel A: offset conv partials (4 channel chunks), fp16 x reads
// ============================================================================
__global__ void offset_conv_part_kernel(const __half* __restrict__ xh,
                                        const float* __restrict__ w) {
    __shared__ float ws[OC18 * CCH * 9];
    int cc = blockIdx.y;
    for (int i = threadIdx.x; i < OC18 * CCH * 9; i += blockDim.x) {
        int oc = i / (CCH * 9);
        int r  = i - oc * (CCH * 9);
        ws[i] = w[oc * KD + cc * (CCH * 9) + r];
    }
    __syncthreads();

    int gid = blockIdx.x * blockDim.x + threadIdx.x;
    int b   = gid >> 12;
    int pix = gid & 4095;
    int y   = pix >> 6;
    int xx  = pix & 63;

    float acc[OC18];
#pragma unroll
    for (int oc = 0; oc < OC18; oc++) acc[oc] = 0.f;

    const __half* xb = xh + (size_t)b * CIN * HW + (size_t)cc * CCH * HW;
    for (int c = 0; c < CCH; c++) {
        const __half* xc = xb + (size_t)c * HW;
        float v[9];
#pragma unroll
        for (int ky = 0; ky < 3; ky++) {
            int yy = y - 1 + ky;
            bool yv = (unsigned)yy < (unsigned)H_;
#pragma unroll
            for (int kx = 0; kx < 3; kx++) {
                int x2 = xx - 1 + kx;
                bool xv = (unsigned)x2 < (unsigned)W_;
                v[ky * 3 + kx] = (yv && xv) ? __half2float(xc[yy * W_ + x2]) : 0.f;
            }
        }
#pragma unroll
        for (int kk = 0; kk < 9; kk++) {
            float xvv = v[kk];
#pragma unroll
            for (int oc = 0; oc < OC18; oc++)
                acc[oc] = fmaf(xvv, ws[oc * (CCH * 9) + c * 9 + kk], acc[oc]);
        }
    }

    float* ob = g_offp + (((size_t)cc * B_ + b) * OC18) * HW + pix;
#pragma unroll
    for (int oc = 0; oc < OC18; oc++) ob[(size_t)oc * HW] = acc[oc];
}

// ============================================================================
// Kernel B: deformable bilinear gather, 2 pixels/thread, fp16 x corners
// ============================================================================
__global__ void gather_kernel(const __half* __restrict__ xh,
                              const float* __restrict__ offset_b,
                              __half* __restrict__ Ph) {
    int gid = blockIdx.x * blockDim.x + threadIdx.x;    // < 147456
    int p2  = gid & 2047;           // pixel pair
    int t   = gid >> 11;            // b*9 + kk
    int kk  = t % 9;
    int b   = t / 9;
    int n0  = p2 * 2;

    float bdy = offset_b[2 * kk + 0];
    float bdx = offset_b[2 * kk + 1];

    int   i00[2], i01[2], i10[2], i11[2];
    float w00[2], w01[2], w10[2], w11[2];

#pragma unroll
    for (int u = 0; u < 2; u++) {
        int n  = n0 + u;
        int y  = n >> 6;
        int xx = n & 63;
        float dy = bdy, dx = bdx;
#pragma unroll
        for (int p = 0; p < NCHK; p++) {
            const float* ob = g_offp + (((size_t)p * B_ + b) * OC18) * HW + n;
            dy += ob[(size_t)(2 * kk + 0) * HW];
            dx += ob[(size_t)(2 * kk + 1) * HW];
        }
        float sy = (float)(y - 1 + kk / 3) + dy;
        float sx = (float)(xx - 1 + kk % 3) + dx;
        float fy = floorf(sy), fx = floorf(sx);
        int y0 = (int)fy, x0 = (int)fx;
        int y1 = y0 + 1, x1 = x0 + 1;
        float wy = sy - fy, wx = sx - fx;
        bool vy0 = (unsigned)y0 < (unsigned)H_;
        bool vy1 = (unsigned)y1 < (unsigned)H_;
        bool vx0 = (unsigned)x0 < (unsigned)W_;
        bool vx1 = (unsigned)x1 < (unsigned)W_;
        int cy0 = min(max(y0, 0), H_ - 1), cy1 = min(max(y1, 0), H_ - 1);
        int cx0 = min(max(x0, 0), W_ - 1), cx1 = min(max(x1, 0), W_ - 1);
        i00[u] = cy0 * W_ + cx0;
        i01[u] = cy0 * W_ + cx1;
        i10[u] = cy1 * W_ + cx0;
        i11[u] = cy1 * W_ + cx1;
        w00[u] = (1.f - wy) * (1.f - wx) * (float)(vy0 && vx0);
        w01[u] = (1.f - wy) * wx         * (float)(vy0 && vx1);
        w10[u] = wy * (1.f - wx)         * (float)(vy1 && vx0);
        w11[u] = wy * wx                 * (float)(vy1 && vx1);
    }

    const __half* xb = xh + (size_t)b * CIN * HW;
    size_t base = ((size_t)b * KD + kk) * HW + n0;

#pragma unroll 2
    for (int c = 0; c < CIN; c++) {
        const __half* xc = xb + (size_t)c * HW;
        size_t idx = base + (size_t)c * (KK9 * HW);
        float v0 = w00[0] * __half2float(xc[i00[0]])
                 + w01[0] * __half2float(xc[i01[0]])
                 + w10[0] * __half2float(xc[i10[0]])
                 + w11[0] * __half2float(xc[i11[0]]);
        float v1 = w00[1] * __half2float(xc[i00[1]])
                 + w01[1] * __half2float(xc[i01[1]])
                 + w10[1] * __half2float(xc[i10[1]])
                 + w11[1] * __half2float(xc[i11[1]]);
        *(__half2*)(Ph + idx) = __floats2half2_rn(v0, v1);
    }
}

// ============================================================================
// Kernel C: HMMA GEMM  Y[b] = W[256,1152] @ P[b][1152,4096] + bias
// Pure fp16 single pass, fp32 accum. BK=64 (18 chunks), 2-stage cp.async,
// loads before wait, launch_bounds(256,2). Fused BN partial sums.
// ============================================================================
#define BK      64
#define NC      (KD / BK)        // 18
#define A_STR   72
#define B_STR   136
#define AH_OFF  0
#define BH_OFF  (128 * A_STR)                // 9216
#define STG     (BH_OFF + BK * B_STR)        // 17920 halves / stage
#define SMEM_GEMM (2 * STG * 2)              // 71680 bytes

__global__ void __launch_bounds__(256, 2)
gemm_mma_kernel(const __half* __restrict__ Wh,
                const __half* __restrict__ Ph,
                const float* __restrict__ bias,
                float* __restrict__ Y) {
    extern __shared__ __half sm[];
    const uint32_t sbase = smem_u32(sm);

    int tid  = threadIdx.x;
    int wid  = tid >> 5;
    int lane = tid & 31;
    int bn = blockIdx.x * 128;
    int bm = blockIdx.y * 128;
    int b  = blockIdx.z;

    int wm = (wid >> 2) * 64;    // warp m offset
    int wn = (wid & 3) * 32;     // warp n offset

    const __half* Pb = Ph + (size_t)b * KD * HW;

    float acc[4][4][4];
#pragma unroll
    for (int i = 0; i < 4; i++)
#pragma unroll
        for (int j = 0; j < 4; j++)
#pragma unroll
            for (int q = 0; q < 4; q++) acc[i][j][q] = 0.f;

    auto load_stage = [&](int chunk, int st) {
        int k0 = chunk * BK;
        uint32_t s0 = sbase + (uint32_t)(st * STG) * 2;
        // A: 128 rows x 64 k
#pragma unroll
        for (int i = 0; i < 4; i++) {
            int idx = tid + i * 256;          // 0..1023
            int m   = idx >> 3;               // 0..127
            int kq  = (idx & 7) << 3;         // 0..56
            size_t go = (size_t)(bm + m) * KD + k0 + kq;
            uint32_t sa = s0 + (uint32_t)(m * A_STR + kq) * 2;
            cpa16(sa + AH_OFF * 2, Wh + go);
        }
        // B: 64 k x 128 n
#pragma unroll
        for (int i = 0; i < 4; i++) {
            int idx = tid + i * 256;
            int k   = idx >> 4;               // 0..63
            int nq  = (idx & 15) << 3;
            size_t go = (size_t)(k0 + k) * HW + bn + nq;
            uint32_t sa = s0 + (uint32_t)(k * B_STR + nq) * 2;
            cpa16(sa + BH_OFF * 2, Pb + go);
        }
        CPA_COMMIT();
    };

    load_stage(0, 0);

    int row  = lane & 15;
    int half = (lane >> 4) << 3;

    for (int c = 0; c < NC; c++) {
        int st = c & 1;
        if (c + 1 < NC) {
            load_stage(c + 1, st ^ 1);   // issue next-stage loads FIRST
            CPA_WAIT(1);
        } else {
            CPA_WAIT(0);
        }
        __syncthreads();

        uint32_t s0 = sbase + (uint32_t)(st * STG) * 2;

#pragma unroll
        for (int ks = 0; ks < BK; ks += 16) {
            uint32_t ah[4][4], bh[4][2];
#pragma unroll
            for (int i = 0; i < 4; i++) {
                uint32_t a = s0 + (uint32_t)((wm + i * 16 + row) * A_STR + ks + half) * 2;
                ldsm4(ah[i], a + AH_OFF * 2);
            }
#pragma unroll
            for (int j = 0; j < 2; j++) {
                uint32_t a = s0 + (uint32_t)((ks + row) * B_STR + wn + j * 16 + half) * 2;
                uint32_t r0, r1, r2, r3;
                ldsm4t(r0, r1, r2, r3, a + BH_OFF * 2);
                bh[2 * j][0] = r0; bh[2 * j][1] = r1;
                bh[2 * j + 1][0] = r2; bh[2 * j + 1][1] = r3;
            }
#pragma unroll
            for (int i = 0; i < 4; i++)
#pragma unroll
                for (int j = 0; j < 4; j++)
                    mma16816(acc[i][j], ah[i], bh[j]);
        }
        __syncthreads();
    }

    // --- epilogue: add bias, write Y, fused BN partial sums ---
    int r  = lane >> 2;
    int c2 = (lane & 3) << 1;
#pragma unroll
    for (int i = 0; i < 4; i++) {
        int m0 = bm + wm + i * 16 + r;
        float b0 = bias[m0];
        float b1 = bias[m0 + 8];
        float* y0 = Y + ((size_t)b * COUT + m0) * HW + bn + wn + c2;
        float* y1 = y0 + (size_t)8 * HW;
        float sA = 0.f, qA = 0.f, sB = 0.f, qB = 0.f;
#pragma unroll
        for (int j = 0; j < 4; j++) {
            float v00 = acc[i][j][0] + b0, v01 = acc[i][j][1] + b0;
            float v10 = acc[i][j][2] + b1, v11 = acc[i][j][3] + b1;
            *(float2*)(y0 + j * 8) = make_float2(v00, v01);
            *(float2*)(y1 + j * 8) = make_float2(v10, v11);
            sA += v00 + v01; qA = fmaf(v00, v00, fmaf(v01, v01, qA));
            sB += v10 + v11; qB = fmaf(v10, v10, fmaf(v11, v11, qB));
        }
#pragma unroll
        for (int mk = 1; mk <= 2; mk <<= 1) {
            sA += __shfl_xor_sync(0xFFFFFFFF, sA, mk);
            qA += __shfl_xor_sync(0xFFFFFFFF, qA, mk);
            sB += __shfl_xor_sync(0xFFFFFFFF, sB, mk);
            qB += __shfl_xor_sync(0xFFFFFFFF, qB, mk);
        }
        if ((lane & 3) == 0) {
            atomicAdd(&g_sum[m0], sA);
            atomicAdd(&g_sqs[m0], qA);
            atomicAdd(&g_sum[m0 + 8], sB);
            atomicAdd(&g_sqs[m0 + 8], qB);
        }
    }
}

// ============================================================================
// Kernel E: normalize + affine + SiLU (in place); per-block inline BN stats.
// o = (i4>>10)&255 is constant within each 256-thread block (1024 alignment).
// ============================================================================
__global__ void bnsilu_kernel(float* __restrict__ Y,
                              const float* __restrict__ gamma,
                              const float* __restrict__ beta) {
    __shared__ float s_m, s_r;
    size_t i4 = (size_t)blockIdx.x * blockDim.x + threadIdx.x;
    int o = (int)((i4 >> 10) & (COUT - 1));
    if (threadIdx.x == 0) {
        const float invN = 1.f / (float)(B_ * HW);
        float m   = g_sum[o] * invN;
        float var = g_sqs[o] * invN - m * m;
        s_m = m;
        s_r = rsqrtf(var + 1e-5f);
    }
    __syncthreads();
    float m = s_m, rs = s_r, g = gamma[o], be = beta[o];
    float4 v = ((float4*)Y)[i4];
    float t;
    t = (v.x - m) * rs * g + be; v.x = t / (1.f + __expf(-t));
    t = (v.y - m) * rs * g + be; v.y = t / (1.f + __expf(-t));
    t = (v.z - m) * rs * g + be; v.z = t / (1.f + __expf(-t));
    t = (v.w - m) * rs * g + be; v.w = t / (1.f + __expf(-t));
    ((float4*)Y)[i4] = v;
}

// ============================================================================
// Launch
// ============================================================================
extern "C" void kernel_launch(void* const* d_in, const int* in_sizes, int n_in,
                              void* d_out, int out_size) {
    const float* x        = (const float*)d_in[0];
    const float* offset_w = (const float*)d_in[1];
    const float* offset_b = (const float*)d_in[2];
    const float* dconv_w  = (const float*)d_in[3];
    const float* dconv_b  = (const float*)d_in[4];
    const float* bn_gamma = (const float*)d_in[5];
    const float* bn_beta  = (const float*)d_in[6];
    float* out = (float*)d_out;

    __half *Ph, *Wh, *Xh;
    cudaGetSymbolAddress((void**)&Ph, g_Ph);
    cudaGetSymbolAddress((void**)&Wh, g_Wh);
    cudaGetSymbolAddress((void**)&Xh, g_xh);

    static bool attr_set = false;
    if (!attr_set) {
        cudaFuncSetAttribute(gemm_mma_kernel,
                             cudaFuncAttributeMaxDynamicSharedMemorySize,
                             SMEM_GEMM);
        attr_set = true;
    }

    // P: x->fp16 + W->fp16 + zero BN accumulators (fused)
    prep_kernel<<<(B_ * CIN * HW / 4) / 256, 256>>>(x, Xh, dconv_w, Wh);

    // A: offset conv partials (fp16 x)
    offset_conv_part_kernel<<<dim3(256, NCHK), 128>>>(Xh, offset_w);

    // B: gather (2 pixels/thread, fp16 x corners, fp16 P)
    gather_kernel<<<(B_ * KK9 * HW / 2) / 256, 256>>>(Xh, offset_b, Ph);

    // C: pure fp16 single-pass HMMA GEMM (BK=64) + fused BN partial sums
    dim3 g(HW / 128, COUT / 128, B_);
    gemm_mma_kernel<<<g, 256, SMEM_GEMM>>>(Wh, Ph, dconv_b, out);

    // E: normalize + SiLU with inline per-block BN stat finalize
    bnsilu_kernel<<<(B_ * COUT * HW / 4) / 256, 256>>>(out, bn_gamma, bn_beta);
}